// round 14
// baseline (speedup 1.0000x reference)
#include <cuda_runtime.h>
#include <cuda_fp16.h>
#include <cstdint>

#define NN_MAX 60000
#define EE_MAX 960000

typedef unsigned long long u64;

__device__ float g_asrc[NN_MAX * 64];
__device__ float g_adst[NN_MAX * 64];
__device__ float g_v[NN_MAX * 64];
__device__ float g_nd[NN_MAX * 128];   // [node][0:64]=num, [64:128]=den

// ---------------- helpers ----------------
__device__ __forceinline__ uint32_t pack_h2(float a, float b) {
    __half2 h = __floats2half2_rn(a, b);
    return *reinterpret_cast<uint32_t*>(&h);
}
__device__ __forceinline__ uint32_t smem_u32(const void* p) {
    uint32_t a;
    asm("{ .reg .u64 t; cvta.to.shared.u64 t, %1; cvt.u32.u64 %0, t; }" : "=r"(a) : "l"(p));
    return a;
}
__device__ __forceinline__ void cp_async16(uint32_t dst, const void* src) {
    asm volatile("cp.async.cg.shared.global [%0], [%1], 16;" :: "r"(dst), "l"(src) : "memory");
}
__device__ __forceinline__ void cp_commit() {
    asm volatile("cp.async.commit_group;" ::: "memory");
}
__device__ __forceinline__ void cp_wait0() {
    asm volatile("cp.async.wait_group 0;" ::: "memory");
}
__device__ __forceinline__ void red_v4(float* p, float a, float b, float c, float d) {
    asm volatile("red.global.add.v4.f32 [%0], {%1,%2,%3,%4};"
                 :: "l"(p), "f"(a), "f"(b), "f"(c), "f"(d) : "memory");
}
// exp(a) for a >= 0 on the FMA pipe (no MUFU)
__device__ __forceinline__ float fexp(float a) {
    float t = a * 1.4426950408889634f;
    float fi = rintf(t);
    float f = t - fi;
    float p = fmaf(f, 1.3333558e-3f, 9.6181291e-3f);
    p = fmaf(p, f, 5.5504109e-2f);
    p = fmaf(p, f, 2.4022651e-1f);
    p = fmaf(p, f, 6.9314718e-1f);
    p = fmaf(p, f, 1.0f);
    return p * __int_as_float(((int)fi + 127) << 23);
}
__device__ __forceinline__ void mma_f16(float* d, uint32_t a0, uint32_t a1,
                                        uint32_t a2, uint32_t a3,
                                        uint32_t b0, uint32_t b1) {
    asm volatile(
        "mma.sync.aligned.m16n8k16.row.col.f32.f16.f16.f32 "
        "{%0,%1,%2,%3}, {%4,%5,%6,%7}, {%8,%9}, {%0,%1,%2,%3};"
        : "+f"(d[0]), "+f"(d[1]), "+f"(d[2]), "+f"(d[3])
        : "r"(a0), "r"(a1), "r"(a2), "r"(a3), "r"(b0), "r"(b1));
}
// GEMM with unpaired B (node kernel): A [128][36 h2], W [n][k/2] stride 36 h2
__device__ __forceinline__ void gemm16h(const uint32_t* __restrict__ Ah,
                                        const uint32_t* __restrict__ Wh,
                                        int warp, int lane, float acc[8][4]) {
    int r0 = warp * 16 + (lane >> 2);
    int a0i = r0 * 36 + (lane & 3);
    int a1i = (r0 + 8) * 36 + (lane & 3);
    #pragma unroll
    for (int k16 = 0; k16 < 4; k16++) {
        uint32_t a0 = Ah[a0i + k16 * 8];
        uint32_t a1 = Ah[a1i + k16 * 8];
        uint32_t a2 = Ah[a0i + k16 * 8 + 4];
        uint32_t a3 = Ah[a1i + k16 * 8 + 4];
        int bb = (lane >> 2) * 36 + (lane & 3) + k16 * 8;
        #pragma unroll
        for (int n = 0; n < 8; n++) {
            mma_f16(acc[n], a0, a1, a2, a3, Wh[bb + n * 288], Wh[bb + n * 288 + 4]);
        }
    }
}
// GEMM with paired-u64 B fragments: Wp[(n*4 + k16)*32 + lane] (one LDS.64 per mma)
__device__ __forceinline__ void gemm16p(const uint32_t* __restrict__ Ah,
                                        const u64* __restrict__ Wp,
                                        int warp, int lane, float acc[8][4]) {
    int r0 = warp * 16 + (lane >> 2);
    int a0i = r0 * 36 + (lane & 3);
    int a1i = (r0 + 8) * 36 + (lane & 3);
    #pragma unroll
    for (int k16 = 0; k16 < 4; k16++) {
        uint32_t a0 = Ah[a0i + k16 * 8];
        uint32_t a1 = Ah[a1i + k16 * 8];
        uint32_t a2 = Ah[a0i + k16 * 8 + 4];
        uint32_t a3 = Ah[a1i + k16 * 8 + 4];
        #pragma unroll
        for (int n = 0; n < 8; n++) {
            u64 w = Wp[(n * 4 + k16) * 32 + lane];
            mma_f16(acc[n], a0, a1, a2, a3, (uint32_t)w, (uint32_t)(w >> 32));
        }
    }
}

// ================= node kernel: f16 mma, 128 nodes/tile =================
struct NSmem {
    uint32_t Wih[64 * 36], Wsh[64 * 36], Wdh[64 * 36], Wlh[64 * 36];
    uint32_t Ah[128 * 36];
    float bin[64], bl[64];
};

__global__ __launch_bounds__(256, 2) void node_mma_kernel(
    const float* __restrict__ x,
    const float* __restrict__ Win, const float* __restrict__ bin,
    const float* __restrict__ Wsrc, const float* __restrict__ Wdst,
    const float* __restrict__ Wlin, const float* __restrict__ blin, int nn)
{
    extern __shared__ char raw[];
    NSmem& s = *reinterpret_cast<NSmem*>(raw);
    int tid = threadIdx.x;
    for (int i = tid; i < 2048; i += 256) {
        int n = i >> 5, k2 = i & 31;
        s.Wih[n * 36 + k2] = pack_h2(Win[(2 * k2) * 64 + n],  Win[(2 * k2 + 1) * 64 + n]);
        s.Wsh[n * 36 + k2] = pack_h2(Wsrc[(2 * k2) * 64 + n], Wsrc[(2 * k2 + 1) * 64 + n]);
        s.Wdh[n * 36 + k2] = pack_h2(Wdst[(2 * k2) * 64 + n], Wdst[(2 * k2 + 1) * 64 + n]);
        s.Wlh[n * 36 + k2] = pack_h2(Wlin[(2 * k2) * 64 + n], Wlin[(2 * k2 + 1) * 64 + n]);
    }
    if (tid < 64) { s.bin[tid] = bin[tid]; s.bl[tid] = blin[tid]; }
    __syncthreads();

    int warp = tid >> 5, lane = tid & 31;
    int wr0 = warp * 16 + (lane >> 2);
    int wr1 = wr0 + 8;
    int ntiles = (nn + 127) / 128;

    for (int tile = blockIdx.x; tile < ntiles; tile += gridDim.x) {
        {
            int row = tid >> 1, h = tid & 1;
            int node = tile * 128 + row;
            if (node < nn) {
                const float4* xr = reinterpret_cast<const float4*>(&x[node * 64 + h * 32]);
                #pragma unroll
                for (int j = 0; j < 8; j++) {
                    float4 v = xr[j];
                    s.Ah[row * 36 + h * 16 + j * 2]     = pack_h2(v.x, v.y);
                    s.Ah[row * 36 + h * 16 + j * 2 + 1] = pack_h2(v.z, v.w);
                }
            } else {
                #pragma unroll
                for (int j = 0; j < 16; j++) s.Ah[row * 36 + h * 16 + j] = 0u;
            }
        }
        __syncwarp();

        float acc[8][4];

        #pragma unroll
        for (int n = 0; n < 8; n++) { acc[n][0] = acc[n][1] = acc[n][2] = acc[n][3] = 0.f; }
        gemm16h(s.Ah, s.Wih, warp, lane, acc);
        __syncwarp();
        #pragma unroll
        for (int n = 0; n < 8; n++) {
            int colb = n * 8 + (lane & 3) * 2;
            int ci = n * 4 + (lane & 3);
            float2 bb = *reinterpret_cast<const float2*>(&s.bin[colb]);
            s.Ah[wr0 * 36 + ci] = pack_h2(fmaxf(acc[n][0] + bb.x, 0.f), fmaxf(acc[n][1] + bb.y, 0.f));
            s.Ah[wr1 * 36 + ci] = pack_h2(fmaxf(acc[n][2] + bb.x, 0.f), fmaxf(acc[n][3] + bb.y, 0.f));
        }
        __syncwarp();

        int node0 = tile * 128 + wr0;
        int node1 = tile * 128 + wr1;
        bool n0ok = node0 < nn, n1ok = node1 < nn;

        #pragma unroll
        for (int n = 0; n < 8; n++) { acc[n][0] = acc[n][1] = acc[n][2] = acc[n][3] = 0.f; }
        gemm16h(s.Ah, s.Wsh, warp, lane, acc);
        #pragma unroll
        for (int n = 0; n < 8; n++) {
            int colb = n * 8 + (lane & 3) * 2;
            if (n0ok) *reinterpret_cast<float2*>(&g_asrc[node0 * 64 + colb]) = make_float2(acc[n][0], acc[n][1]);
            if (n1ok) *reinterpret_cast<float2*>(&g_asrc[node1 * 64 + colb]) = make_float2(acc[n][2], acc[n][3]);
        }

        #pragma unroll
        for (int n = 0; n < 8; n++) { acc[n][0] = acc[n][1] = acc[n][2] = acc[n][3] = 0.f; }
        gemm16h(s.Ah, s.Wdh, warp, lane, acc);
        #pragma unroll
        for (int n = 0; n < 8; n++) {
            int colb = n * 8 + (lane & 3) * 2;
            if (n0ok) *reinterpret_cast<float2*>(&g_adst[node0 * 64 + colb]) = make_float2(acc[n][0], acc[n][1]);
            if (n1ok) *reinterpret_cast<float2*>(&g_adst[node1 * 64 + colb]) = make_float2(acc[n][2], acc[n][3]);
        }

        #pragma unroll
        for (int n = 0; n < 8; n++) { acc[n][0] = acc[n][1] = acc[n][2] = acc[n][3] = 0.f; }
        gemm16h(s.Ah, s.Wlh, warp, lane, acc);
        #pragma unroll
        for (int n = 0; n < 8; n++) {
            int colb = n * 8 + (lane & 3) * 2;
            float2 bb = *reinterpret_cast<const float2*>(&s.bl[colb]);
            if (n0ok) *reinterpret_cast<float2*>(&g_v[node0 * 64 + colb]) = make_float2(acc[n][0] + bb.x, acc[n][1] + bb.y);
            if (n1ok) *reinterpret_cast<float2*>(&g_v[node1 * 64 + colb]) = make_float2(acc[n][2] + bb.x, acc[n][3] + bb.y);
        }

        {
            float* base = &g_nd[(size_t)tile * 128 * 128];
            for (int i = tid; i < 4096; i += 256) {
                int node = tile * 128 + (i >> 5);
                if (node < nn)
                    *reinterpret_cast<float4*>(base + i * 4) = make_float4(0.f, 0.f, 0.f, 0.f);
            }
        }
        __syncwarp();
    }
}

// ================= edge kernel: cp.async gather prefetch + paired-B + reg-delta =================
struct ESmem {
    u64 W2p[1024], W3p[1024], W4p[1024];   // 24576 B
    float PaD[128 * 68];                    // 34816 B  (prefetched a_dst rows)
    float PaS[128 * 68];                    // 34816 B  (prefetched a_src rows)
    uint32_t Ah[128 * 36];                  // 18432 B
    float Wp1[192], b1[64], b2[64], b3[64], b4[64];   // 1792 B
};  // total 114432 B = 111.75 KB -> 2 CTAs/SM

__global__ __launch_bounds__(256, 2) void edge_mma_kernel(
    const float* __restrict__ pos, const int* __restrict__ ei,
    const float* __restrict__ Wp1, const float* __restrict__ bp1,
    const float* __restrict__ Wp2, const float* __restrict__ bp2,
    const float* __restrict__ Wa1, const float* __restrict__ ba1,
    const float* __restrict__ Wa2, const float* __restrict__ ba2, int ne)
{
    extern __shared__ char raw[];
    ESmem& s = *reinterpret_cast<ESmem*>(raw);
    int tid = threadIdx.x;

    for (int i = tid; i < 1024; i += 256) {
        int k16 = (i >> 5) & 3, ln = i & 31;
        int n = ((i >> 7) << 3) + (ln >> 2);
        int h = k16 * 8 + (ln & 3);
        int r0 = 2 * h, r1 = 2 * h + 1, r2 = 2 * h + 8, r3 = 2 * h + 9;
        {
            uint32_t b0 = pack_h2(Wp2[r0 * 64 + n], Wp2[r1 * 64 + n]);
            uint32_t b1 = pack_h2(Wp2[r2 * 64 + n], Wp2[r3 * 64 + n]);
            s.W2p[i] = ((u64)b1 << 32) | b0;
        }
        {
            uint32_t b0 = pack_h2(Wa1[r0 * 64 + n], Wa1[r1 * 64 + n]);
            uint32_t b1 = pack_h2(Wa1[r2 * 64 + n], Wa1[r3 * 64 + n]);
            s.W3p[i] = ((u64)b1 << 32) | b0;
        }
        {
            uint32_t b0 = pack_h2(Wa2[r0 * 64 + n], Wa2[r1 * 64 + n]);
            uint32_t b1 = pack_h2(Wa2[r2 * 64 + n], Wa2[r3 * 64 + n]);
            s.W4p[i] = ((u64)b1 << 32) | b0;
        }
    }
    if (tid < 192) s.Wp1[tid] = Wp1[tid];
    if (tid < 64) { s.b1[tid] = bp1[tid]; s.b2[tid] = bp2[tid]; s.b3[tid] = ba1[tid]; s.b4[tid] = ba2[tid]; }
    __syncthreads();

    int warp = tid >> 5, lane = tid & 31;
    uint32_t padD = smem_u32(s.PaD);
    uint32_t padS = smem_u32(s.PaS);
    int ntiles = (ne + 127) / 128;

    for (int tile = blockIdx.x; tile < ntiles; tile += gridDim.x) {
        // ---- per-warp meta in REGISTERS: lanes 0-15 hold this warp's 16 edge-rows ----
        int msi = 0, mdi = 0;
        float mp0 = 0.f, mp1 = 0.f, mp2 = 0.f;
        if (lane < 16) {
            int ed = tile * 128 + warp * 16 + lane;
            if (ed < ne) {
                msi = ei[ed]; mdi = ei[ne + ed];
                mp0 = pos[mdi * 3 + 0] - pos[msi * 3 + 0];
                mp1 = pos[mdi * 3 + 1] - pos[msi * 3 + 1];
                mp2 = pos[mdi * 3 + 2] - pos[msi * 3 + 2];
            }
        }
        __syncwarp();

        // ---- cp.async prefetch a_dst[di]/a_src[si] rows into PaD/PaS ----
        {
            int prow = lane >> 1;                 // 0..15 local row
            int row = warp * 16 + prow;
            int dir = __shfl_sync(0xffffffffu, mdi, prow);
            int sir = __shfl_sync(0xffffffffu, msi, prow);
            int cc0 = (lane & 1) * 8;
            #pragma unroll
            for (int c = 0; c < 8; c++) {
                int chunk = cc0 + c;
                cp_async16(padD + (uint32_t)(row * 68 + chunk * 4) * 4,
                           &g_adst[dir * 64 + chunk * 4]);
                cp_async16(padS + (uint32_t)(row * 68 + chunk * 4) * 4,
                           &g_asrc[sir * 64 + chunk * 4]);
            }
            cp_commit();
        }

        // ---- stage0: h1 = relu(pd @ Wp1 + b1) -> Ah (f16) ----
        {
            int row = warp * 16 + (lane >> 1);
            int ch = (lane & 1) * 32;
            float p0 = __shfl_sync(0xffffffffu, mp0, lane >> 1);
            float p1 = __shfl_sync(0xffffffffu, mp1, lane >> 1);
            float p2 = __shfl_sync(0xffffffffu, mp2, lane >> 1);
            #pragma unroll
            for (int j = 0; j < 8; j++) {
                int c = ch + j * 4;
                float4 w0 = *reinterpret_cast<const float4*>(&s.Wp1[c]);
                float4 w1 = *reinterpret_cast<const float4*>(&s.Wp1[64 + c]);
                float4 w2 = *reinterpret_cast<const float4*>(&s.Wp1[128 + c]);
                float4 bb = *reinterpret_cast<const float4*>(&s.b1[c]);
                float ox = fmaxf(fmaf(p2, w2.x, fmaf(p1, w1.x, fmaf(p0, w0.x, bb.x))), 0.f);
                float oy = fmaxf(fmaf(p2, w2.y, fmaf(p1, w1.y, fmaf(p0, w0.y, bb.y))), 0.f);
                float oz = fmaxf(fmaf(p2, w2.z, fmaf(p1, w1.z, fmaf(p0, w0.z, bb.z))), 0.f);
                float ow = fmaxf(fmaf(p2, w2.w, fmaf(p1, w1.w, fmaf(p0, w0.w, bb.w))), 0.f);
                s.Ah[row * 36 + c / 2]     = pack_h2(ox, oy);
                s.Ah[row * 36 + c / 2 + 1] = pack_h2(oz, ow);
            }
        }
        __syncwarp();

        int wr0 = warp * 16 + (lane >> 2);
        int wr1 = wr0 + 8;
        int si0 = __shfl_sync(0xffffffffu, msi, lane >> 2);
        int di0 = __shfl_sync(0xffffffffu, mdi, lane >> 2);
        int si1 = __shfl_sync(0xffffffffu, msi, (lane >> 2) + 8);
        int di1 = __shfl_sync(0xffffffffu, mdi, (lane >> 2) + 8);

        float acc[8][4];
        #pragma unroll
        for (int n = 0; n < 8; n++) { acc[n][0] = acc[n][1] = acc[n][2] = acc[n][3] = 0.f; }
        gemm16p(s.Ah, s.W2p, warp, lane, acc);

        cp_wait0();
        __syncwarp();

        // ---- epi1: delta = relu(.+b2) -> regs; q = PaD-PaS+delta -> Ah ----
        float dl[8][4];
        #pragma unroll
        for (int n = 0; n < 8; n++) {
            int colb = n * 8 + (lane & 3) * 2;
            int ci = n * 4 + (lane & 3);
            float2 b2v = *reinterpret_cast<const float2*>(&s.b2[colb]);
            float2 ad0 = *reinterpret_cast<const float2*>(&s.PaD[wr0 * 68 + colb]);
            float2 as0 = *reinterpret_cast<const float2*>(&s.PaS[wr0 * 68 + colb]);
            dl[n][0] = fmaxf(acc[n][0] + b2v.x, 0.f);
            dl[n][1] = fmaxf(acc[n][1] + b2v.y, 0.f);
            s.Ah[wr0 * 36 + ci] = pack_h2(ad0.x - as0.x + dl[n][0], ad0.y - as0.y + dl[n][1]);
            float2 ad1 = *reinterpret_cast<const float2*>(&s.PaD[wr1 * 68 + colb]);
            float2 as1 = *reinterpret_cast<const float2*>(&s.PaS[wr1 * 68 + colb]);
            dl[n][2] = fmaxf(acc[n][2] + b2v.x, 0.f);
            dl[n][3] = fmaxf(acc[n][3] + b2v.y, 0.f);
            s.Ah[wr1 * 36 + ci] = pack_h2(ad1.x - as1.x + dl[n][2], ad1.y - as1.y + dl[n][3]);
        }
        __syncwarp();

        #pragma unroll
        for (int n = 0; n < 8; n++) { acc[n][0] = acc[n][1] = acc[n][2] = acc[n][3] = 0.f; }
        gemm16p(s.Ah, s.W3p, warp, lane, acc);
        __syncwarp();

        // ---- epi2: t = relu(.+b3) -> Ah ----
        #pragma unroll
        for (int n = 0; n < 8; n++) {
            int colb = n * 8 + (lane & 3) * 2;
            int ci = n * 4 + (lane & 3);
            float2 b3v = *reinterpret_cast<const float2*>(&s.b3[colb]);
            s.Ah[wr0 * 36 + ci] = pack_h2(fmaxf(acc[n][0] + b3v.x, 0.f), fmaxf(acc[n][1] + b3v.y, 0.f));
            s.Ah[wr1 * 36 + ci] = pack_h2(fmaxf(acc[n][2] + b3v.x, 0.f), fmaxf(acc[n][3] + b3v.y, 0.f));
        }
        __syncwarp();

        // ---- prefetch v[src] (covers final GEMM latency) ----
        float2 vv0[8], vv1[8];
        #pragma unroll
        for (int n = 0; n < 8; n++) {
            int colb = n * 8 + (lane & 3) * 2;
            vv0[n] = *reinterpret_cast<const float2*>(&g_v[si0 * 64 + colb]);
            vv1[n] = *reinterpret_cast<const float2*>(&g_v[si1 * 64 + colb]);
        }

        #pragma unroll
        for (int n = 0; n < 8; n++) { acc[n][0] = acc[n][1] = acc[n][2] = acc[n][3] = 0.f; }
        gemm16p(s.Ah, s.W4p, warp, lane, acc);

        // ---- epi3: p = fexp(relu(.+b4)); num = p*(v+delta); vector RED ----
        bool v0 = (tile * 128 + wr0) < ne;
        bool v1 = (tile * 128 + wr1) < ne;
        bool even = ((lane & 1) == 0);
        #pragma unroll
        for (int n = 0; n < 8; n++) {
            int colb = n * 8 + (lane & 3) * 2;
            float2 b4v = *reinterpret_cast<const float2*>(&s.b4[colb]);
            {
                float p0 = fexp(fmaxf(acc[n][0] + b4v.x, 0.f));
                float p1 = fexp(fmaxf(acc[n][1] + b4v.y, 0.f));
                float num0 = p0 * (vv0[n].x + dl[n][0]);
                float num1 = p1 * (vv0[n].y + dl[n][1]);
                float sa = even ? p0 : num0;
                float sb = even ? p1 : num1;
                float ra = __shfl_xor_sync(0xffffffffu, sa, 1);
                float rb = __shfl_xor_sync(0xffffffffu, sb, 1);
                if (v0) {
                    float* nd = &g_nd[di0 * 128];
                    if (even) red_v4(&nd[colb], num0, num1, ra, rb);
                    else      red_v4(&nd[64 + colb - 2], ra, rb, p0, p1);
                }
            }
            {
                float p0 = fexp(fmaxf(acc[n][2] + b4v.x, 0.f));
                float p1 = fexp(fmaxf(acc[n][3] + b4v.y, 0.f));
                float num0 = p0 * (vv1[n].x + dl[n][2]);
                float num1 = p1 * (vv1[n].y + dl[n][3]);
                float sa = even ? p0 : num0;
                float sb = even ? p1 : num1;
                float ra = __shfl_xor_sync(0xffffffffu, sa, 1);
                float rb = __shfl_xor_sync(0xffffffffu, sb, 1);
                if (v1) {
                    float* nd = &g_nd[di1 * 128];
                    if (even) red_v4(&nd[colb], num0, num1, ra, rb);
                    else      red_v4(&nd[64 + colb - 2], ra, rb, p0, p1);
                }
            }
        }
        __syncwarp();
    }
}

// ================= out kernel =================
struct OutSmem {
    float W[4096];
    float b[64];
    float rs[8][64];
};

__global__ __launch_bounds__(256, 3) void out_kernel(
    const float* __restrict__ Wout, const float* __restrict__ bout,
    float* __restrict__ out, int nn)
{
    extern __shared__ char raw[];
    OutSmem& s = *reinterpret_cast<OutSmem*>(raw);
    int tid = threadIdx.x;
    for (int i = tid; i < 4096; i += 256) s.W[i] = Wout[i];
    if (tid < 64) s.b[tid] = bout[tid];
    __syncthreads();

    int warp = tid >> 5, lane = tid & 31, c0 = lane * 2;
    int totW = (gridDim.x * 256) >> 5;
    for (int node = (blockIdx.x * 256 + tid) >> 5; node < nn; node += totW) {
        float2 nm = *reinterpret_cast<float2*>(&g_nd[node * 128 + c0]);
        float2 dn = *reinterpret_cast<float2*>(&g_nd[node * 128 + 64 + c0]);
        float r0 = nm.x / (dn.x + 1e-16f);
        float r1 = nm.y / (dn.y + 1e-16f);
        s.rs[warp][c0] = r0; s.rs[warp][c0 + 1] = r1;
        __syncwarp();
        float o0 = s.b[c0], o1 = s.b[c0 + 1];
        #pragma unroll 16
        for (int k = 0; k < 64; k++) {
            float rk = s.rs[warp][k];
            float2 w = *reinterpret_cast<float2*>(&s.W[k * 64 + c0]);
            o0 = fmaf(rk, w.x, o0); o1 = fmaf(rk, w.y, o1);
        }
        *reinterpret_cast<float2*>(&out[node * 64 + c0]) =
            make_float2(fmaxf(o0, 0.f), fmaxf(o1, 0.f));
        __syncwarp();
    }
}

// ================= launch =================
extern "C" void kernel_launch(void* const* d_in, const int* in_sizes, int n_in,
                              void* d_out, int out_size)
{
    const float* x     = (const float*)d_in[0];
    const float* pos   = (const float*)d_in[1];
    const float* W_in  = (const float*)d_in[2];
    const float* b_in  = (const float*)d_in[3];
    const float* W_src = (const float*)d_in[4];
    const float* W_dst = (const float*)d_in[5];
    const float* W_lin = (const float*)d_in[6];
    const float* b_lin = (const float*)d_in[7];
    const float* Wp1   = (const float*)d_in[8];
    const float* bp1   = (const float*)d_in[9];
    const float* Wp2   = (const float*)d_in[10];
    const float* bp2   = (const float*)d_in[11];
    const float* Wa1   = (const float*)d_in[12];
    const float* ba1   = (const float*)d_in[13];
    const float* Wa2   = (const float*)d_in[14];
    const float* ba2   = (const float*)d_in[15];
    const float* W_out = (const float*)d_in[16];
    const float* b_out = (const float*)d_in[17];
    const int*   ei    = (const int*)d_in[18];
    float* out = (float*)d_out;

    int nn = in_sizes[0] / 64;
    int ne = in_sizes[18] / 2;

    cudaFuncSetAttribute(node_mma_kernel, cudaFuncAttributeMaxDynamicSharedMemorySize, (int)sizeof(NSmem));
    cudaFuncSetAttribute(edge_mma_kernel, cudaFuncAttributeMaxDynamicSharedMemorySize, (int)sizeof(ESmem));
    cudaFuncSetAttribute(out_kernel,  cudaFuncAttributeMaxDynamicSharedMemorySize, (int)sizeof(OutSmem));

    node_mma_kernel<<<296, 256, sizeof(NSmem)>>>(x, W_in, b_in, W_src, W_dst, W_lin, b_lin, nn);
    edge_mma_kernel<<<296, 256, sizeof(ESmem)>>>(pos, ei, Wp1, bp1, Wp2, bp2, Wa1, ba1, Wa2, ba2, ne);
    out_kernel<<<592, 256, sizeof(OutSmem)>>>(W_out, b_out, out, nn);
}

// round 15
// speedup vs baseline: 1.1922x; 1.1922x over previous
#include <cuda_runtime.h>
#include <cuda_fp16.h>
#include <cstdint>

#define NN_MAX 60000
#define EE_MAX 960000

typedef unsigned long long u64;

__device__ float g_asrc[NN_MAX * 64];
__device__ float g_adst[NN_MAX * 64];
__device__ float g_v[NN_MAX * 64];
__device__ float g_nd[NN_MAX * 128];   // [node][0:64]=num, [64:128]=den

// ---------------- helpers ----------------
__device__ __forceinline__ uint32_t pack_h2(float a, float b) {
    __half2 h = __floats2half2_rn(a, b);
    return *reinterpret_cast<uint32_t*>(&h);
}
__device__ __forceinline__ uint32_t smem_u32(const void* p) {
    uint32_t a;
    asm("{ .reg .u64 t; cvta.to.shared.u64 t, %1; cvt.u32.u64 %0, t; }" : "=r"(a) : "l"(p));
    return a;
}
__device__ __forceinline__ void red_v4(float* p, float a, float b, float c, float d) {
    asm volatile("red.global.add.v4.f32 [%0], {%1,%2,%3,%4};"
                 :: "l"(p), "f"(a), "f"(b), "f"(c), "f"(d) : "memory");
}
// exp(a) for a >= 0 on the FMA pipe (no MUFU)
__device__ __forceinline__ float fexp(float a) {
    float t = a * 1.4426950408889634f;
    float fi = rintf(t);
    float f = t - fi;
    float p = fmaf(f, 1.3333558e-3f, 9.6181291e-3f);
    p = fmaf(p, f, 5.5504109e-2f);
    p = fmaf(p, f, 2.4022651e-1f);
    p = fmaf(p, f, 6.9314718e-1f);
    p = fmaf(p, f, 1.0f);
    return p * __int_as_float(((int)fi + 127) << 23);
}
__device__ __forceinline__ void mma_f16(float* d, uint32_t a0, uint32_t a1,
                                        uint32_t a2, uint32_t a3,
                                        uint32_t b0, uint32_t b1) {
    asm volatile(
        "mma.sync.aligned.m16n8k16.row.col.f32.f16.f16.f32 "
        "{%0,%1,%2,%3}, {%4,%5,%6,%7}, {%8,%9}, {%0,%1,%2,%3};"
        : "+f"(d[0]), "+f"(d[1]), "+f"(d[2]), "+f"(d[3])
        : "r"(a0), "r"(a1), "r"(a2), "r"(a3), "r"(b0), "r"(b1));
}
__device__ __forceinline__ void ldmatrix_x4(uint32_t& a0, uint32_t& a1,
                                            uint32_t& a2, uint32_t& a3, uint32_t addr) {
    asm volatile("ldmatrix.sync.aligned.m8n8.x4.shared.b16 {%0,%1,%2,%3}, [%4];"
                 : "=r"(a0), "=r"(a1), "=r"(a2), "=r"(a3) : "r"(addr));
}
// per-thread ldmatrix base address for the m16k16 A fragment of this warp's rows.
// lane group g = lane>>3: g&1 -> +8 rows (a1/a3), g>>1 -> +16B (k halves 8-15, a2/a3)
__device__ __forceinline__ uint32_t ldmA_base(uint32_t AhAddr, int warp, int lane) {
    int row = warp * 16 + ((lane >> 3) & 1) * 8 + (lane & 7);
    return AhAddr + (uint32_t)row * 144u + (uint32_t)((lane >> 4) & 1) * 16u;
}
// GEMM with ldmatrix A + unpaired B (node): W [n][k/2] stride 36 h2
__device__ __forceinline__ void gemm16h(uint32_t aBase,
                                        const uint32_t* __restrict__ Wh,
                                        int lane, float acc[8][4]) {
    #pragma unroll
    for (int k16 = 0; k16 < 4; k16++) {
        uint32_t a0, a1, a2, a3;
        ldmatrix_x4(a0, a1, a2, a3, aBase + (uint32_t)k16 * 32u);
        int bb = (lane >> 2) * 36 + (lane & 3) + k16 * 8;
        #pragma unroll
        for (int n = 0; n < 8; n++) {
            mma_f16(acc[n], a0, a1, a2, a3, Wh[bb + n * 288], Wh[bb + n * 288 + 4]);
        }
    }
}
// GEMM with ldmatrix A + paired-u64 B fragments: Wp[(n*4 + k16)*32 + lane]
__device__ __forceinline__ void gemm16p(uint32_t aBase,
                                        const u64* __restrict__ Wp,
                                        int lane, float acc[8][4]) {
    #pragma unroll
    for (int k16 = 0; k16 < 4; k16++) {
        uint32_t a0, a1, a2, a3;
        ldmatrix_x4(a0, a1, a2, a3, aBase + (uint32_t)k16 * 32u);
        #pragma unroll
        for (int n = 0; n < 8; n++) {
            u64 w = Wp[(n * 4 + k16) * 32 + lane];
            mma_f16(acc[n], a0, a1, a2, a3, (uint32_t)w, (uint32_t)(w >> 32));
        }
    }
}

// ================= node kernel: f16 mma, 128 nodes/tile =================
struct NSmem {
    uint32_t Wih[64 * 36], Wsh[64 * 36], Wdh[64 * 36], Wlh[64 * 36];
    uint32_t Ah[128 * 36];
    float bin[64], bl[64];
};

__global__ __launch_bounds__(256, 2) void node_mma_kernel(
    const float* __restrict__ x,
    const float* __restrict__ Win, const float* __restrict__ bin,
    const float* __restrict__ Wsrc, const float* __restrict__ Wdst,
    const float* __restrict__ Wlin, const float* __restrict__ blin, int nn)
{
    extern __shared__ char raw[];
    NSmem& s = *reinterpret_cast<NSmem*>(raw);
    int tid = threadIdx.x;
    for (int i = tid; i < 2048; i += 256) {
        int n = i >> 5, k2 = i & 31;
        s.Wih[n * 36 + k2] = pack_h2(Win[(2 * k2) * 64 + n],  Win[(2 * k2 + 1) * 64 + n]);
        s.Wsh[n * 36 + k2] = pack_h2(Wsrc[(2 * k2) * 64 + n], Wsrc[(2 * k2 + 1) * 64 + n]);
        s.Wdh[n * 36 + k2] = pack_h2(Wdst[(2 * k2) * 64 + n], Wdst[(2 * k2 + 1) * 64 + n]);
        s.Wlh[n * 36 + k2] = pack_h2(Wlin[(2 * k2) * 64 + n], Wlin[(2 * k2 + 1) * 64 + n]);
    }
    if (tid < 64) { s.bin[tid] = bin[tid]; s.bl[tid] = blin[tid]; }
    __syncthreads();

    int warp = tid >> 5, lane = tid & 31;
    int wr0 = warp * 16 + (lane >> 2);
    int wr1 = wr0 + 8;
    uint32_t aBase = ldmA_base(smem_u32(s.Ah), warp, lane);
    int ntiles = (nn + 127) / 128;

    for (int tile = blockIdx.x; tile < ntiles; tile += gridDim.x) {
        {
            int row = tid >> 1, h = tid & 1;
            int node = tile * 128 + row;
            if (node < nn) {
                const float4* xr = reinterpret_cast<const float4*>(&x[node * 64 + h * 32]);
                #pragma unroll
                for (int j = 0; j < 8; j++) {
                    float4 v = xr[j];
                    s.Ah[row * 36 + h * 16 + j * 2]     = pack_h2(v.x, v.y);
                    s.Ah[row * 36 + h * 16 + j * 2 + 1] = pack_h2(v.z, v.w);
                }
            } else {
                #pragma unroll
                for (int j = 0; j < 16; j++) s.Ah[row * 36 + h * 16 + j] = 0u;
            }
        }
        __syncwarp();

        float acc[8][4];

        #pragma unroll
        for (int n = 0; n < 8; n++) { acc[n][0] = acc[n][1] = acc[n][2] = acc[n][3] = 0.f; }
        gemm16h(aBase, s.Wih, lane, acc);
        __syncwarp();
        #pragma unroll
        for (int n = 0; n < 8; n++) {
            int colb = n * 8 + (lane & 3) * 2;
            int ci = n * 4 + (lane & 3);
            float2 bb = *reinterpret_cast<const float2*>(&s.bin[colb]);
            s.Ah[wr0 * 36 + ci] = pack_h2(fmaxf(acc[n][0] + bb.x, 0.f), fmaxf(acc[n][1] + bb.y, 0.f));
            s.Ah[wr1 * 36 + ci] = pack_h2(fmaxf(acc[n][2] + bb.x, 0.f), fmaxf(acc[n][3] + bb.y, 0.f));
        }
        __syncwarp();

        int node0 = tile * 128 + wr0;
        int node1 = tile * 128 + wr1;
        bool n0ok = node0 < nn, n1ok = node1 < nn;

        #pragma unroll
        for (int n = 0; n < 8; n++) { acc[n][0] = acc[n][1] = acc[n][2] = acc[n][3] = 0.f; }
        gemm16h(aBase, s.Wsh, lane, acc);
        #pragma unroll
        for (int n = 0; n < 8; n++) {
            int colb = n * 8 + (lane & 3) * 2;
            if (n0ok) *reinterpret_cast<float2*>(&g_asrc[node0 * 64 + colb]) = make_float2(acc[n][0], acc[n][1]);
            if (n1ok) *reinterpret_cast<float2*>(&g_asrc[node1 * 64 + colb]) = make_float2(acc[n][2], acc[n][3]);
        }

        #pragma unroll
        for (int n = 0; n < 8; n++) { acc[n][0] = acc[n][1] = acc[n][2] = acc[n][3] = 0.f; }
        gemm16h(aBase, s.Wdh, lane, acc);
        #pragma unroll
        for (int n = 0; n < 8; n++) {
            int colb = n * 8 + (lane & 3) * 2;
            if (n0ok) *reinterpret_cast<float2*>(&g_adst[node0 * 64 + colb]) = make_float2(acc[n][0], acc[n][1]);
            if (n1ok) *reinterpret_cast<float2*>(&g_adst[node1 * 64 + colb]) = make_float2(acc[n][2], acc[n][3]);
        }

        #pragma unroll
        for (int n = 0; n < 8; n++) { acc[n][0] = acc[n][1] = acc[n][2] = acc[n][3] = 0.f; }
        gemm16h(aBase, s.Wlh, lane, acc);
        #pragma unroll
        for (int n = 0; n < 8; n++) {
            int colb = n * 8 + (lane & 3) * 2;
            float2 bb = *reinterpret_cast<const float2*>(&s.bl[colb]);
            if (n0ok) *reinterpret_cast<float2*>(&g_v[node0 * 64 + colb]) = make_float2(acc[n][0] + bb.x, acc[n][1] + bb.y);
            if (n1ok) *reinterpret_cast<float2*>(&g_v[node1 * 64 + colb]) = make_float2(acc[n][2] + bb.x, acc[n][3] + bb.y);
        }

        {
            float* base = &g_nd[(size_t)tile * 128 * 128];
            for (int i = tid; i < 4096; i += 256) {
                int node = tile * 128 + (i >> 5);
                if (node < nn)
                    *reinterpret_cast<float4*>(base + i * 4) = make_float4(0.f, 0.f, 0.f, 0.f);
            }
        }
        __syncwarp();
    }
}

// ================= edge kernel: paired-B + ldmatrix-A + reg-delta (round-12 structure) =================
struct ESmem {
    u64 W2p[1024], W3p[1024], W4p[1024];   // [nt][k16][lane] paired B fragments
    uint32_t Ah[128 * 36];
    float Wp1[192], b1[64], b2[64], b3[64], b4[64];
    float px[128], py[128], pz[128];
    int si[128], di[128];
};

__global__ __launch_bounds__(256, 2) void edge_mma_kernel(
    const float* __restrict__ pos, const int* __restrict__ ei,
    const float* __restrict__ Wp1, const float* __restrict__ bp1,
    const float* __restrict__ Wp2, const float* __restrict__ bp2,
    const float* __restrict__ Wa1, const float* __restrict__ ba1,
    const float* __restrict__ Wa2, const float* __restrict__ ba2, int ne)
{
    extern __shared__ char raw[];
    ESmem& s = *reinterpret_cast<ESmem*>(raw);
    int tid = threadIdx.x;

    for (int i = tid; i < 1024; i += 256) {
        int k16 = (i >> 5) & 3, ln = i & 31;
        int n = ((i >> 7) << 3) + (ln >> 2);
        int h = k16 * 8 + (ln & 3);
        int r0 = 2 * h, r1 = 2 * h + 1, r2 = 2 * h + 8, r3 = 2 * h + 9;
        {
            uint32_t b0 = pack_h2(Wp2[r0 * 64 + n], Wp2[r1 * 64 + n]);
            uint32_t b1 = pack_h2(Wp2[r2 * 64 + n], Wp2[r3 * 64 + n]);
            s.W2p[i] = ((u64)b1 << 32) | b0;
        }
        {
            uint32_t b0 = pack_h2(Wa1[r0 * 64 + n], Wa1[r1 * 64 + n]);
            uint32_t b1 = pack_h2(Wa1[r2 * 64 + n], Wa1[r3 * 64 + n]);
            s.W3p[i] = ((u64)b1 << 32) | b0;
        }
        {
            uint32_t b0 = pack_h2(Wa2[r0 * 64 + n], Wa2[r1 * 64 + n]);
            uint32_t b1 = pack_h2(Wa2[r2 * 64 + n], Wa2[r3 * 64 + n]);
            s.W4p[i] = ((u64)b1 << 32) | b0;
        }
    }
    if (tid < 192) s.Wp1[tid] = Wp1[tid];
    if (tid < 64) { s.b1[tid] = bp1[tid]; s.b2[tid] = bp2[tid]; s.b3[tid] = ba1[tid]; s.b4[tid] = ba2[tid]; }
    __syncthreads();

    int warp = tid >> 5, lane = tid & 31;
    uint32_t aBase = ldmA_base(smem_u32(s.Ah), warp, lane);
    int ntiles = (ne + 127) / 128;

    for (int tile = blockIdx.x; tile < ntiles; tile += gridDim.x) {
        // ---- per-warp meta: lanes 0-15 load this warp's 16 edge-rows ----
        if (lane < 16) {
            int row = warp * 16 + lane;
            int ed = tile * 128 + row;
            int si = 0, di = 0;
            float p0 = 0.f, p1 = 0.f, p2 = 0.f;
            if (ed < ne) {
                si = ei[ed]; di = ei[ne + ed];
                p0 = pos[di * 3 + 0] - pos[si * 3 + 0];
                p1 = pos[di * 3 + 1] - pos[si * 3 + 1];
                p2 = pos[di * 3 + 2] - pos[si * 3 + 2];
            }
            s.si[row] = si; s.di[row] = di;
            s.px[row] = p0; s.py[row] = p1; s.pz[row] = p2;
        }
        __syncwarp();

        // ---- stage0: h1 = relu(pd @ Wp1 + b1) -> Ah (f16) ----
        {
            int row = warp * 16 + (lane >> 1);
            int ch = (lane & 1) * 32;
            float p0 = s.px[row], p1 = s.py[row], p2 = s.pz[row];
            #pragma unroll
            for (int j = 0; j < 8; j++) {
                int c = ch + j * 4;
                float4 w0 = *reinterpret_cast<const float4*>(&s.Wp1[c]);
                float4 w1 = *reinterpret_cast<const float4*>(&s.Wp1[64 + c]);
                float4 w2 = *reinterpret_cast<const float4*>(&s.Wp1[128 + c]);
                float4 bb = *reinterpret_cast<const float4*>(&s.b1[c]);
                float ox = fmaxf(fmaf(p2, w2.x, fmaf(p1, w1.x, fmaf(p0, w0.x, bb.x))), 0.f);
                float oy = fmaxf(fmaf(p2, w2.y, fmaf(p1, w1.y, fmaf(p0, w0.y, bb.y))), 0.f);
                float oz = fmaxf(fmaf(p2, w2.z, fmaf(p1, w1.z, fmaf(p0, w0.z, bb.z))), 0.f);
                float ow = fmaxf(fmaf(p2, w2.w, fmaf(p1, w1.w, fmaf(p0, w0.w, bb.w))), 0.f);
                s.Ah[row * 36 + c / 2]     = pack_h2(ox, oy);
                s.Ah[row * 36 + c / 2 + 1] = pack_h2(oz, ow);
            }
        }
        __syncwarp();

        int wr0 = warp * 16 + (lane >> 2);
        int wr1 = wr0 + 8;
        int si0 = s.si[wr0], di0 = s.di[wr0];
        int si1 = s.si[wr1], di1 = s.di[wr1];

        float acc[8][4];
        #pragma unroll
        for (int n = 0; n < 8; n++) { acc[n][0] = acc[n][1] = acc[n][2] = acc[n][3] = 0.f; }
        gemm16p(aBase, s.W2p, lane, acc);
        __syncwarp();

        // ---- epi1: delta = relu(.+b2) -> regs; q = adst-asrc+delta -> Ah ----
        float dl[8][4];
        #pragma unroll
        for (int n = 0; n < 8; n++) {
            int colb = n * 8 + (lane & 3) * 2;
            int ci = n * 4 + (lane & 3);
            float2 b2v = *reinterpret_cast<const float2*>(&s.b2[colb]);
            float2 ad0 = *reinterpret_cast<const float2*>(&g_adst[di0 * 64 + colb]);
            float2 as0 = *reinterpret_cast<const float2*>(&g_asrc[si0 * 64 + colb]);
            dl[n][0] = fmaxf(acc[n][0] + b2v.x, 0.f);
            dl[n][1] = fmaxf(acc[n][1] + b2v.y, 0.f);
            s.Ah[wr0 * 36 + ci] = pack_h2(ad0.x - as0.x + dl[n][0], ad0.y - as0.y + dl[n][1]);
            float2 ad1 = *reinterpret_cast<const float2*>(&g_adst[di1 * 64 + colb]);
            float2 as1 = *reinterpret_cast<const float2*>(&g_asrc[si1 * 64 + colb]);
            dl[n][2] = fmaxf(acc[n][2] + b2v.x, 0.f);
            dl[n][3] = fmaxf(acc[n][3] + b2v.y, 0.f);
            s.Ah[wr1 * 36 + ci] = pack_h2(ad1.x - as1.x + dl[n][2], ad1.y - as1.y + dl[n][3]);
        }
        __syncwarp();

        #pragma unroll
        for (int n = 0; n < 8; n++) { acc[n][0] = acc[n][1] = acc[n][2] = acc[n][3] = 0.f; }
        gemm16p(aBase, s.W3p, lane, acc);
        __syncwarp();

        // ---- epi2: t = relu(.+b3) -> Ah ----
        #pragma unroll
        for (int n = 0; n < 8; n++) {
            int colb = n * 8 + (lane & 3) * 2;
            int ci = n * 4 + (lane & 3);
            float2 b3v = *reinterpret_cast<const float2*>(&s.b3[colb]);
            s.Ah[wr0 * 36 + ci] = pack_h2(fmaxf(acc[n][0] + b3v.x, 0.f), fmaxf(acc[n][1] + b3v.y, 0.f));
            s.Ah[wr1 * 36 + ci] = pack_h2(fmaxf(acc[n][2] + b3v.x, 0.f), fmaxf(acc[n][3] + b3v.y, 0.f));
        }
        __syncwarp();

        // ---- prefetch v[src] (covers final GEMM latency) ----
        float2 vv0[8], vv1[8];
        #pragma unroll
        for (int n = 0; n < 8; n++) {
            int colb = n * 8 + (lane & 3) * 2;
            vv0[n] = *reinterpret_cast<const float2*>(&g_v[si0 * 64 + colb]);
            vv1[n] = *reinterpret_cast<const float2*>(&g_v[si1 * 64 + colb]);
        }

        #pragma unroll
        for (int n = 0; n < 8; n++) { acc[n][0] = acc[n][1] = acc[n][2] = acc[n][3] = 0.f; }
        gemm16p(aBase, s.W4p, lane, acc);

        // ---- epi3: p = fexp(relu(.+b4)); num = p*(v+delta); vector RED ----
        bool v0 = (tile * 128 + wr0) < ne;
        bool v1 = (tile * 128 + wr1) < ne;
        bool even = ((lane & 1) == 0);
        #pragma unroll
        for (int n = 0; n < 8; n++) {
            int colb = n * 8 + (lane & 3) * 2;
            float2 b4v = *reinterpret_cast<const float2*>(&s.b4[colb]);
            {
                float p0 = fexp(fmaxf(acc[n][0] + b4v.x, 0.f));
                float p1 = fexp(fmaxf(acc[n][1] + b4v.y, 0.f));
                float num0 = p0 * (vv0[n].x + dl[n][0]);
                float num1 = p1 * (vv0[n].y + dl[n][1]);
                float sa = even ? p0 : num0;
                float sb = even ? p1 : num1;
                float ra = __shfl_xor_sync(0xffffffffu, sa, 1);
                float rb = __shfl_xor_sync(0xffffffffu, sb, 1);
                if (v0) {
                    float* nd = &g_nd[di0 * 128];
                    if (even) red_v4(&nd[colb], num0, num1, ra, rb);
                    else      red_v4(&nd[64 + colb - 2], ra, rb, p0, p1);
                }
            }
            {
                float p0 = fexp(fmaxf(acc[n][2] + b4v.x, 0.f));
                float p1 = fexp(fmaxf(acc[n][3] + b4v.y, 0.f));
                float num0 = p0 * (vv1[n].x + dl[n][2]);
                float num1 = p1 * (vv1[n].y + dl[n][3]);
                float sa = even ? p0 : num0;
                float sb = even ? p1 : num1;
                float ra = __shfl_xor_sync(0xffffffffu, sa, 1);
                float rb = __shfl_xor_sync(0xffffffffu, sb, 1);
                if (v1) {
                    float* nd = &g_nd[di1 * 128];
                    if (even) red_v4(&nd[colb], num0, num1, ra, rb);
                    else      red_v4(&nd[64 + colb - 2], ra, rb, p0, p1);
                }
            }
        }
        __syncwarp();
    }
}

// ================= out kernel =================
struct OutSmem {
    float W[4096];
    float b[64];
    float rs[8][64];
};

__global__ __launch_bounds__(256, 3) void out_kernel(
    const float* __restrict__ Wout, const float* __restrict__ bout,
    float* __restrict__ out, int nn)
{
    extern __shared__ char raw[];
    OutSmem& s = *reinterpret_cast<OutSmem*>(raw);
    int tid = threadIdx.x;
    for (int i = tid; i < 4096; i += 256) s.W[i] = Wout[i];
    if (tid < 64) s.b[tid] = bout[tid];
    __syncthreads();

    int warp = tid >> 5, lane = tid & 31, c0 = lane * 2;
    int totW = (gridDim.x * 256) >> 5;
    for (int node = (blockIdx.x * 256 + tid) >> 5; node < nn; node += totW) {
        float2 nm = *reinterpret_cast<float2*>(&g_nd[node * 128 + c0]);
        float2 dn = *reinterpret_cast<float2*>(&g_nd[node * 128 + 64 + c0]);
        float r0 = nm.x / (dn.x + 1e-16f);
        float r1 = nm.y / (dn.y + 1e-16f);
        s.rs[warp][c0] = r0; s.rs[warp][c0 + 1] = r1;
        __syncwarp();
        float o0 = s.b[c0], o1 = s.b[c0 + 1];
        #pragma unroll 16
        for (int k = 0; k < 64; k++) {
            float rk = s.rs[warp][k];
            float2 w = *reinterpret_cast<float2*>(&s.W[k * 64 + c0]);
            o0 = fmaf(rk, w.x, o0); o1 = fmaf(rk, w.y, o1);
        }
        *reinterpret_cast<float2*>(&out[node * 64 + c0]) =
            make_float2(fmaxf(o0, 0.f), fmaxf(o1, 0.f));
        __syncwarp();
    }
}

// ================= launch =================
extern "C" void kernel_launch(void* const* d_in, const int* in_sizes, int n_in,
                              void* d_out, int out_size)
{
    const float* x     = (const float*)d_in[0];
    const float* pos   = (const float*)d_in[1];
    const float* W_in  = (const float*)d_in[2];
    const float* b_in  = (const float*)d_in[3];
    const float* W_src = (const float*)d_in[4];
    const float* W_dst = (const float*)d_in[5];
    const float* W_lin = (const float*)d_in[6];
    const float* b_lin = (const float*)d_in[7];
    const float* Wp1   = (const float*)d_in[8];
    const float* bp1   = (const float*)d_in[9];
    const float* Wp2   = (const float*)d_in[10];
    const float* bp2   = (const float*)d_in[11];
    const float* Wa1   = (const float*)d_in[12];
    const float* ba1   = (const float*)d_in[13];
    const float* Wa2   = (const float*)d_in[14];
    const float* ba2   = (const float*)d_in[15];
    const float* W_out = (const float*)d_in[16];
    const float* b_out = (const float*)d_in[17];
    const int*   ei    = (const int*)d_in[18];
    float* out = (float*)d_out;

    int nn = in_sizes[0] / 64;
    int ne = in_sizes[18] / 2;

    cudaFuncSetAttribute(node_mma_kernel, cudaFuncAttributeMaxDynamicSharedMemorySize, (int)sizeof(NSmem));
    cudaFuncSetAttribute(edge_mma_kernel, cudaFuncAttributeMaxDynamicSharedMemorySize, (int)sizeof(ESmem));
    cudaFuncSetAttribute(out_kernel,  cudaFuncAttributeMaxDynamicSharedMemorySize, (int)sizeof(OutSmem));

    node_mma_kernel<<<296, 256, sizeof(NSmem)>>>(x, W_in, b_in, W_src, W_dst, W_lin, b_lin, nn);
    edge_mma_kernel<<<296, 256, sizeof(ESmem)>>>(pos, ei, Wp1, bp1, Wp2, bp2, Wa1, ba1, Wa2, ba2, ne);
    out_kernel<<<592, 256, sizeof(OutSmem)>>>(W_out, b_out, out, nn);
}

// round 16
// speedup vs baseline: 1.4057x; 1.1791x over previous
#include <cuda_runtime.h>
#include <cuda_fp16.h>
#include <cstdint>

#define NN_MAX 60000
#define EE_MAX 960000

typedef unsigned long long u64;

__device__ float g_asrc[NN_MAX * 64];
__device__ float g_adst[NN_MAX * 64];
__device__ float g_v[NN_MAX * 64];
__device__ float g_nd[NN_MAX * 128];   // [node][0:64]=num, [64:128]=den

// ---------------- helpers ----------------
__device__ __forceinline__ uint32_t pack_h2(float a, float b) {
    __half2 h = __floats2half2_rn(a, b);
    return *reinterpret_cast<uint32_t*>(&h);
}
__device__ __forceinline__ uint32_t smem_u32(const void* p) {
    uint32_t a;
    asm("{ .reg .u64 t; cvta.to.shared.u64 t, %1; cvt.u32.u64 %0, t; }" : "=r"(a) : "l"(p));
    return a;
}
__device__ __forceinline__ void red_v4(float* p, float a, float b, float c, float d) {
    asm volatile("red.global.add.v4.f32 [%0], {%1,%2,%3,%4};"
                 :: "l"(p), "f"(a), "f"(b), "f"(c), "f"(d) : "memory");
}
// exp(a) for a >= 0 on the FMA pipe (no MUFU)
__device__ __forceinline__ float fexp(float a) {
    float t = a * 1.4426950408889634f;
    float fi = rintf(t);
    float f = t - fi;
    float p = fmaf(f, 1.3333558e-3f, 9.6181291e-3f);
    p = fmaf(p, f, 5.5504109e-2f);
    p = fmaf(p, f, 2.4022651e-1f);
    p = fmaf(p, f, 6.9314718e-1f);
    p = fmaf(p, f, 1.0f);
    return p * __int_as_float(((int)fi + 127) << 23);
}
__device__ __forceinline__ void mma_f16(float* d, uint32_t a0, uint32_t a1,
                                        uint32_t a2, uint32_t a3,
                                        uint32_t b0, uint32_t b1) {
    asm volatile(
        "mma.sync.aligned.m16n8k16.row.col.f32.f16.f16.f32 "
        "{%0,%1,%2,%3}, {%4,%5,%6,%7}, {%8,%9}, {%0,%1,%2,%3};"
        : "+f"(d[0]), "+f"(d[1]), "+f"(d[2]), "+f"(d[3])
        : "r"(a0), "r"(a1), "r"(a2), "r"(a3), "r"(b0), "r"(b1));
}
__device__ __forceinline__ void ldmatrix_x4(uint32_t& a0, uint32_t& a1,
                                            uint32_t& a2, uint32_t& a3, uint32_t addr) {
    asm volatile("ldmatrix.sync.aligned.m8n8.x4.shared.b16 {%0,%1,%2,%3}, [%4];"
                 : "=r"(a0), "=r"(a1), "=r"(a2), "=r"(a3) : "r"(addr));
}
__device__ __forceinline__ uint32_t ldmA_base(uint32_t AhAddr, int warp, int lane) {
    int row = warp * 16 + ((lane >> 3) & 1) * 8 + (lane & 7);
    return AhAddr + (uint32_t)row * 144u + (uint32_t)((lane >> 4) & 1) * 16u;
}
// GEMM: ldmatrix A + paired-u64 B: Wp[(n*4 + k16)*32 + lane]
__device__ __forceinline__ void gemm16p(uint32_t aBase,
                                        const u64* __restrict__ Wp,
                                        int lane, float acc[8][4]) {
    #pragma unroll
    for (int k16 = 0; k16 < 4; k16++) {
        uint32_t a0, a1, a2, a3;
        ldmatrix_x4(a0, a1, a2, a3, aBase + (uint32_t)k16 * 32u);
        #pragma unroll
        for (int n = 0; n < 8; n++) {
            u64 w = Wp[(n * 4 + k16) * 32 + lane];
            mma_f16(acc[n], a0, a1, a2, a3, (uint32_t)w, (uint32_t)(w >> 32));
        }
    }
}
// GEMM: register A (D->A direct pass) + paired-u64 B
__device__ __forceinline__ void gemm16r(const uint32_t ar[4][4],
                                        const u64* __restrict__ Wp,
                                        int lane, float acc[8][4]) {
    #pragma unroll
    for (int k16 = 0; k16 < 4; k16++) {
        #pragma unroll
        for (int n = 0; n < 8; n++) {
            u64 w = Wp[(n * 4 + k16) * 32 + lane];
            mma_f16(acc[n], ar[k16][0], ar[k16][1], ar[k16][2], ar[k16][3],
                    (uint32_t)w, (uint32_t)(w >> 32));
        }
    }
}
// build paired-B fragment table from a row-major [k][n] fp32 weight
__device__ __forceinline__ u64 pairB(const float* W, int i) {
    int k16 = (i >> 5) & 3, ln = i & 31;
    int n = ((i >> 7) << 3) + (ln >> 2);
    int h = k16 * 8 + (ln & 3);
    uint32_t b0 = pack_h2(W[(2 * h) * 64 + n],     W[(2 * h + 1) * 64 + n]);
    uint32_t b1 = pack_h2(W[(2 * h + 8) * 64 + n], W[(2 * h + 9) * 64 + n]);
    return ((u64)b1 << 32) | b0;
}

// ================= node kernel: f16 mma, reg-chained GEMMs 2-4 =================
struct NSmem {
    u64 Wip[1024], Wsp[1024], Wdp[1024], Wlp[1024];
    uint32_t Ah[128 * 36];
    float bin[64], bl[64];
};

__global__ __launch_bounds__(256, 2) void node_mma_kernel(
    const float* __restrict__ x,
    const float* __restrict__ Win, const float* __restrict__ bin,
    const float* __restrict__ Wsrc, const float* __restrict__ Wdst,
    const float* __restrict__ Wlin, const float* __restrict__ blin, int nn)
{
    extern __shared__ char raw[];
    NSmem& s = *reinterpret_cast<NSmem*>(raw);
    int tid = threadIdx.x;
    for (int i = tid; i < 1024; i += 256) {
        s.Wip[i] = pairB(Win, i);
        s.Wsp[i] = pairB(Wsrc, i);
        s.Wdp[i] = pairB(Wdst, i);
        s.Wlp[i] = pairB(Wlin, i);
    }
    if (tid < 64) { s.bin[tid] = bin[tid]; s.bl[tid] = blin[tid]; }
    __syncthreads();

    int warp = tid >> 5, lane = tid & 31;
    int wr0 = warp * 16 + (lane >> 2);
    int wr1 = wr0 + 8;
    uint32_t aBase = ldmA_base(smem_u32(s.Ah), warp, lane);
    int ntiles = (nn + 127) / 128;

    for (int tile = blockIdx.x; tile < ntiles; tile += gridDim.x) {
        {
            int row = tid >> 1, h = tid & 1;
            int node = tile * 128 + row;
            if (node < nn) {
                const float4* xr = reinterpret_cast<const float4*>(&x[node * 64 + h * 32]);
                #pragma unroll
                for (int j = 0; j < 8; j++) {
                    float4 v = xr[j];
                    s.Ah[row * 36 + h * 16 + j * 2]     = pack_h2(v.x, v.y);
                    s.Ah[row * 36 + h * 16 + j * 2 + 1] = pack_h2(v.z, v.w);
                }
            } else {
                #pragma unroll
                for (int j = 0; j < 16; j++) s.Ah[row * 36 + h * 16 + j] = 0u;
            }
        }
        __syncwarp();

        float acc[8][4];
        #pragma unroll
        for (int n = 0; n < 8; n++) { acc[n][0] = acc[n][1] = acc[n][2] = acc[n][3] = 0.f; }
        gemm16p(aBase, s.Wip, lane, acc);

        // h = relu(acc + bin) -> A registers (D->A direct)
        uint32_t ar[4][4];
        #pragma unroll
        for (int n = 0; n < 8; n++) {
            int colb = n * 8 + (lane & 3) * 2;
            float2 bb = *reinterpret_cast<const float2*>(&s.bin[colb]);
            ar[n >> 1][(n & 1) * 2 + 0] =
                pack_h2(fmaxf(acc[n][0] + bb.x, 0.f), fmaxf(acc[n][1] + bb.y, 0.f));
            ar[n >> 1][(n & 1) * 2 + 1] =
                pack_h2(fmaxf(acc[n][2] + bb.x, 0.f), fmaxf(acc[n][3] + bb.y, 0.f));
        }

        int node0 = tile * 128 + wr0;
        int node1 = tile * 128 + wr1;
        bool n0ok = node0 < nn, n1ok = node1 < nn;

        #pragma unroll
        for (int n = 0; n < 8; n++) { acc[n][0] = acc[n][1] = acc[n][2] = acc[n][3] = 0.f; }
        gemm16r(ar, s.Wsp, lane, acc);
        #pragma unroll
        for (int n = 0; n < 8; n++) {
            int colb = n * 8 + (lane & 3) * 2;
            if (n0ok) *reinterpret_cast<float2*>(&g_asrc[node0 * 64 + colb]) = make_float2(acc[n][0], acc[n][1]);
            if (n1ok) *reinterpret_cast<float2*>(&g_asrc[node1 * 64 + colb]) = make_float2(acc[n][2], acc[n][3]);
        }

        #pragma unroll
        for (int n = 0; n < 8; n++) { acc[n][0] = acc[n][1] = acc[n][2] = acc[n][3] = 0.f; }
        gemm16r(ar, s.Wdp, lane, acc);
        #pragma unroll
        for (int n = 0; n < 8; n++) {
            int colb = n * 8 + (lane & 3) * 2;
            if (n0ok) *reinterpret_cast<float2*>(&g_adst[node0 * 64 + colb]) = make_float2(acc[n][0], acc[n][1]);
            if (n1ok) *reinterpret_cast<float2*>(&g_adst[node1 * 64 + colb]) = make_float2(acc[n][2], acc[n][3]);
        }

        #pragma unroll
        for (int n = 0; n < 8; n++) { acc[n][0] = acc[n][1] = acc[n][2] = acc[n][3] = 0.f; }
        gemm16r(ar, s.Wlp, lane, acc);
        #pragma unroll
        for (int n = 0; n < 8; n++) {
            int colb = n * 8 + (lane & 3) * 2;
            float2 bb = *reinterpret_cast<const float2*>(&s.bl[colb]);
            if (n0ok) *reinterpret_cast<float2*>(&g_v[node0 * 64 + colb]) = make_float2(acc[n][0] + bb.x, acc[n][1] + bb.y);
            if (n1ok) *reinterpret_cast<float2*>(&g_v[node1 * 64 + colb]) = make_float2(acc[n][2] + bb.x, acc[n][3] + bb.y);
        }

        {
            float* base = &g_nd[(size_t)tile * 128 * 128];
            for (int i = tid; i < 4096; i += 256) {
                int node = tile * 128 + (i >> 5);
                if (node < nn)
                    *reinterpret_cast<float4*>(base + i * 4) = make_float4(0.f, 0.f, 0.f, 0.f);
            }
        }
        __syncwarp();
    }
}

// ================= edge kernel: fully register-chained GEMMs =================
struct ESmem {
    u64 W2p[1024], W3p[1024], W4p[1024];
    float Wp1[192], b1[64], b2[64], b3[64], b4[64];
    float px[128], py[128], pz[128];
    int si[128], di[128];
};

__global__ __launch_bounds__(256, 2) void edge_mma_kernel(
    const float* __restrict__ pos, const int* __restrict__ ei,
    const float* __restrict__ Wp1, const float* __restrict__ bp1,
    const float* __restrict__ Wp2, const float* __restrict__ bp2,
    const float* __restrict__ Wa1, const float* __restrict__ ba1,
    const float* __restrict__ Wa2, const float* __restrict__ ba2, int ne)
{
    extern __shared__ char raw[];
    ESmem& s = *reinterpret_cast<ESmem*>(raw);
    int tid = threadIdx.x;

    for (int i = tid; i < 1024; i += 256) {
        s.W2p[i] = pairB(Wp2, i);
        s.W3p[i] = pairB(Wa1, i);
        s.W4p[i] = pairB(Wa2, i);
    }
    if (tid < 192) s.Wp1[tid] = Wp1[tid];
    if (tid < 64) { s.b1[tid] = bp1[tid]; s.b2[tid] = bp2[tid]; s.b3[tid] = ba1[tid]; s.b4[tid] = ba2[tid]; }
    __syncthreads();

    int warp = tid >> 5, lane = tid & 31;
    int ntiles = (ne + 127) / 128;

    for (int tile = blockIdx.x; tile < ntiles; tile += gridDim.x) {
        // ---- per-warp meta: lanes 0-15 load this warp's 16 edge-rows ----
        if (lane < 16) {
            int row = warp * 16 + lane;
            int ed = tile * 128 + row;
            int si = 0, di = 0;
            float p0 = 0.f, p1 = 0.f, p2 = 0.f;
            if (ed < ne) {
                si = ei[ed]; di = ei[ne + ed];
                p0 = pos[di * 3 + 0] - pos[si * 3 + 0];
                p1 = pos[di * 3 + 1] - pos[si * 3 + 1];
                p2 = pos[di * 3 + 2] - pos[si * 3 + 2];
            }
            s.si[row] = si; s.di[row] = di;
            s.px[row] = p0; s.py[row] = p1; s.pz[row] = p2;
        }
        __syncwarp();

        int wr0 = warp * 16 + (lane >> 2);
        int wr1 = wr0 + 8;
        int si0 = s.si[wr0], di0 = s.di[wr0];
        int si1 = s.si[wr1], di1 = s.di[wr1];

        // ---- stage0: h1 = relu(pd @ Wp1 + b1) directly in A-fragment registers ----
        uint32_t ar[4][4];
        {
            float pa0 = s.px[wr0], pa1 = s.py[wr0], pa2 = s.pz[wr0];
            float pb0 = s.px[wr1], pb1 = s.py[wr1], pb2 = s.pz[wr1];
            #pragma unroll
            for (int n = 0; n < 8; n++) {
                int c = n * 8 + (lane & 3) * 2;
                float2 w0 = *reinterpret_cast<const float2*>(&s.Wp1[c]);
                float2 w1 = *reinterpret_cast<const float2*>(&s.Wp1[64 + c]);
                float2 w2 = *reinterpret_cast<const float2*>(&s.Wp1[128 + c]);
                float2 bb = *reinterpret_cast<const float2*>(&s.b1[c]);
                float h00 = fmaxf(fmaf(pa2, w2.x, fmaf(pa1, w1.x, fmaf(pa0, w0.x, bb.x))), 0.f);
                float h01 = fmaxf(fmaf(pa2, w2.y, fmaf(pa1, w1.y, fmaf(pa0, w0.y, bb.y))), 0.f);
                float h10 = fmaxf(fmaf(pb2, w2.x, fmaf(pb1, w1.x, fmaf(pb0, w0.x, bb.x))), 0.f);
                float h11 = fmaxf(fmaf(pb2, w2.y, fmaf(pb1, w1.y, fmaf(pb0, w0.y, bb.y))), 0.f);
                ar[n >> 1][(n & 1) * 2 + 0] = pack_h2(h00, h01);
                ar[n >> 1][(n & 1) * 2 + 1] = pack_h2(h10, h11);
            }
        }

        float acc[8][4];
        #pragma unroll
        for (int n = 0; n < 8; n++) { acc[n][0] = acc[n][1] = acc[n][2] = acc[n][3] = 0.f; }
        gemm16r(ar, s.W2p, lane, acc);

        // ---- epi1: delta = relu(.+b2) -> regs; q = adst-asrc+delta -> A regs ----
        float dl[8][4];
        #pragma unroll
        for (int n = 0; n < 8; n++) {
            int colb = n * 8 + (lane & 3) * 2;
            float2 b2v = *reinterpret_cast<const float2*>(&s.b2[colb]);
            float2 ad0 = *reinterpret_cast<const float2*>(&g_adst[di0 * 64 + colb]);
            float2 as0 = *reinterpret_cast<const float2*>(&g_asrc[si0 * 64 + colb]);
            dl[n][0] = fmaxf(acc[n][0] + b2v.x, 0.f);
            dl[n][1] = fmaxf(acc[n][1] + b2v.y, 0.f);
            ar[n >> 1][(n & 1) * 2 + 0] =
                pack_h2(ad0.x - as0.x + dl[n][0], ad0.y - as0.y + dl[n][1]);
            float2 ad1 = *reinterpret_cast<const float2*>(&g_adst[di1 * 64 + colb]);
            float2 as1 = *reinterpret_cast<const float2*>(&g_asrc[si1 * 64 + colb]);
            dl[n][2] = fmaxf(acc[n][2] + b2v.x, 0.f);
            dl[n][3] = fmaxf(acc[n][3] + b2v.y, 0.f);
            ar[n >> 1][(n & 1) * 2 + 1] =
                pack_h2(ad1.x - as1.x + dl[n][2], ad1.y - as1.y + dl[n][3]);
        }

        #pragma unroll
        for (int n = 0; n < 8; n++) { acc[n][0] = acc[n][1] = acc[n][2] = acc[n][3] = 0.f; }
        gemm16r(ar, s.W3p, lane, acc);

        // ---- epi2: t = relu(.+b3) -> A regs ----
        #pragma unroll
        for (int n = 0; n < 8; n++) {
            int colb = n * 8 + (lane & 3) * 2;
            float2 b3v = *reinterpret_cast<const float2*>(&s.b3[colb]);
            ar[n >> 1][(n & 1) * 2 + 0] =
                pack_h2(fmaxf(acc[n][0] + b3v.x, 0.f), fmaxf(acc[n][1] + b3v.y, 0.f));
            ar[n >> 1][(n & 1) * 2 + 1] =
                pack_h2(fmaxf(acc[n][2] + b3v.x, 0.f), fmaxf(acc[n][3] + b3v.y, 0.f));
        }

        // ---- prefetch v[src] (covers final GEMM latency) ----
        float2 vv0[8], vv1[8];
        #pragma unroll
        for (int n = 0; n < 8; n++) {
            int colb = n * 8 + (lane & 3) * 2;
            vv0[n] = *reinterpret_cast<const float2*>(&g_v[si0 * 64 + colb]);
            vv1[n] = *reinterpret_cast<const float2*>(&g_v[si1 * 64 + colb]);
        }

        #pragma unroll
        for (int n = 0; n < 8; n++) { acc[n][0] = acc[n][1] = acc[n][2] = acc[n][3] = 0.f; }
        gemm16r(ar, s.W4p, lane, acc);

        // ---- epi3: p = fexp(relu(.+b4)); num = p*(v+delta); vector RED ----
        bool v0 = (tile * 128 + wr0) < ne;
        bool v1 = (tile * 128 + wr1) < ne;
        bool even = ((lane & 1) == 0);
        #pragma unroll
        for (int n = 0; n < 8; n++) {
            int colb = n * 8 + (lane & 3) * 2;
            float2 b4v = *reinterpret_cast<const float2*>(&s.b4[colb]);
            {
                float p0 = fexp(fmaxf(acc[n][0] + b4v.x, 0.f));
                float p1 = fexp(fmaxf(acc[n][1] + b4v.y, 0.f));
                float num0 = p0 * (vv0[n].x + dl[n][0]);
                float num1 = p1 * (vv0[n].y + dl[n][1]);
                float sa = even ? p0 : num0;
                float sb = even ? p1 : num1;
                float ra = __shfl_xor_sync(0xffffffffu, sa, 1);
                float rb = __shfl_xor_sync(0xffffffffu, sb, 1);
                if (v0) {
                    float* nd = &g_nd[di0 * 128];
                    if (even) red_v4(&nd[colb], num0, num1, ra, rb);
                    else      red_v4(&nd[64 + colb - 2], ra, rb, p0, p1);
                }
            }
            {
                float p0 = fexp(fmaxf(acc[n][2] + b4v.x, 0.f));
                float p1 = fexp(fmaxf(acc[n][3] + b4v.y, 0.f));
                float num0 = p0 * (vv1[n].x + dl[n][2]);
                float num1 = p1 * (vv1[n].y + dl[n][3]);
                float sa = even ? p0 : num0;
                float sb = even ? p1 : num1;
                float ra = __shfl_xor_sync(0xffffffffu, sa, 1);
                float rb = __shfl_xor_sync(0xffffffffu, sb, 1);
                if (v1) {
                    float* nd = &g_nd[di1 * 128];
                    if (even) red_v4(&nd[colb], num0, num1, ra, rb);
                    else      red_v4(&nd[64 + colb - 2], ra, rb, p0, p1);
                }
            }
        }
        __syncwarp();
    }
}

// ================= out kernel =================
struct OutSmem {
    float W[4096];
    float b[64];
    float rs[8][64];
};

__global__ __launch_bounds__(256, 3) void out_kernel(
    const float* __restrict__ Wout, const float* __restrict__ bout,
    float* __restrict__ out, int nn)
{
    extern __shared__ char raw[];
    OutSmem& s = *reinterpret_cast<OutSmem*>(raw);
    int tid = threadIdx.x;
    for (int i = tid; i < 4096; i += 256) s.W[i] = Wout[i];
    if (tid < 64) s.b[tid] = bout[tid];
    __syncthreads();

    int warp = tid >> 5, lane = tid & 31, c0 = lane * 2;
    int totW = (gridDim.x * 256) >> 5;
    for (int node = (blockIdx.x * 256 + tid) >> 5; node < nn; node += totW) {
        float2 nm = *reinterpret_cast<float2*>(&g_nd[node * 128 + c0]);
        float2 dn = *reinterpret_cast<float2*>(&g_nd[node * 128 + 64 + c0]);
        float r0 = nm.x / (dn.x + 1e-16f);
        float r1 = nm.y / (dn.y + 1e-16f);
        s.rs[warp][c0] = r0; s.rs[warp][c0 + 1] = r1;
        __syncwarp();
        float o0 = s.b[c0], o1 = s.b[c0 + 1];
        #pragma unroll 16
        for (int k = 0; k < 64; k++) {
            float rk = s.rs[warp][k];
            float2 w = *reinterpret_cast<float2*>(&s.W[k * 64 + c0]);
            o0 = fmaf(rk, w.x, o0); o1 = fmaf(rk, w.y, o1);
        }
        *reinterpret_cast<float2*>(&out[node * 64 + c0]) =
            make_float2(fmaxf(o0, 0.f), fmaxf(o1, 0.f));
        __syncwarp();
    }
}

// ================= launch =================
extern "C" void kernel_launch(void* const* d_in, const int* in_sizes, int n_in,
                              void* d_out, int out_size)
{
    const float* x     = (const float*)d_in[0];
    const float* pos   = (const float*)d_in[1];
    const float* W_in  = (const float*)d_in[2];
    const float* b_in  = (const float*)d_in[3];
    const float* W_src = (const float*)d_in[4];
    const float* W_dst = (const float*)d_in[5];
    const float* W_lin = (const float*)d_in[6];
    const float* b_lin = (const float*)d_in[7];
    const float* Wp1   = (const float*)d_in[8];
    const float* bp1   = (const float*)d_in[9];
    const float* Wp2   = (const float*)d_in[10];
    const float* bp2   = (const float*)d_in[11];
    const float* Wa1   = (const float*)d_in[12];
    const float* ba1   = (const float*)d_in[13];
    const float* Wa2   = (const float*)d_in[14];
    const float* ba2   = (const float*)d_in[15];
    const float* W_out = (const float*)d_in[16];
    const float* b_out = (const float*)d_in[17];
    const int*   ei    = (const int*)d_in[18];
    float* out = (float*)d_out;

    int nn = in_sizes[0] / 64;
    int ne = in_sizes[18] / 2;

    cudaFuncSetAttribute(node_mma_kernel, cudaFuncAttributeMaxDynamicSharedMemorySize, (int)sizeof(NSmem));
    cudaFuncSetAttribute(edge_mma_kernel, cudaFuncAttributeMaxDynamicSharedMemorySize, (int)sizeof(ESmem));
    cudaFuncSetAttribute(out_kernel,  cudaFuncAttributeMaxDynamicSharedMemorySize, (int)sizeof(OutSmem));

    node_mma_kernel<<<296, 256, sizeof(NSmem)>>>(x, W_in, b_in, W_src, W_dst, W_lin, b_lin, nn);
    edge_mma_kernel<<<296, 256, sizeof(ESmem)>>>(pos, ei, Wp1, bp1, Wp2, bp2, Wa1, ba1, Wa2, ba2, ne);
    out_kernel<<<592, 256, sizeof(OutSmem)>>>(W_out, b_out, out, nn);
}

// round 17
// speedup vs baseline: 1.4304x; 1.0176x over previous
#include <cuda_runtime.h>
#include <cuda_fp16.h>
#include <cstdint>

#define NN_MAX 60000
#define EE_MAX 960000

typedef unsigned long long u64;

// f16 (half2-packed) node arrays: halves L2 gather traffic
__device__ uint32_t g_asrc[NN_MAX * 32];
__device__ uint32_t g_adst[NN_MAX * 32];
__device__ uint32_t g_v[NN_MAX * 32];
__device__ float g_nd[NN_MAX * 128];   // [node][0:64]=num, [64:128]=den

// ---------------- helpers ----------------
__device__ __forceinline__ uint32_t pack_h2(float a, float b) {
    __half2 h = __floats2half2_rn(a, b);
    return *reinterpret_cast<uint32_t*>(&h);
}
__device__ __forceinline__ float2 unpack_h2(uint32_t u) {
    return __half22float2(*reinterpret_cast<__half2*>(&u));
}
__device__ __forceinline__ uint32_t smem_u32(const void* p) {
    uint32_t a;
    asm("{ .reg .u64 t; cvta.to.shared.u64 t, %1; cvt.u32.u64 %0, t; }" : "=r"(a) : "l"(p));
    return a;
}
__device__ __forceinline__ void red_v4(float* p, float a, float b, float c, float d) {
    asm volatile("red.global.add.v4.f32 [%0], {%1,%2,%3,%4};"
                 :: "l"(p), "f"(a), "f"(b), "f"(c), "f"(d) : "memory");
}
// exp(a) for a >= 0 on the FMA pipe (no MUFU)
__device__ __forceinline__ float fexp(float a) {
    float t = a * 1.4426950408889634f;
    float fi = rintf(t);
    float f = t - fi;
    float p = fmaf(f, 1.3333558e-3f, 9.6181291e-3f);
    p = fmaf(p, f, 5.5504109e-2f);
    p = fmaf(p, f, 2.4022651e-1f);
    p = fmaf(p, f, 6.9314718e-1f);
    p = fmaf(p, f, 1.0f);
    return p * __int_as_float(((int)fi + 127) << 23);
}
__device__ __forceinline__ void mma_f16(float* d, uint32_t a0, uint32_t a1,
                                        uint32_t a2, uint32_t a3,
                                        uint32_t b0, uint32_t b1) {
    asm volatile(
        "mma.sync.aligned.m16n8k16.row.col.f32.f16.f16.f32 "
        "{%0,%1,%2,%3}, {%4,%5,%6,%7}, {%8,%9}, {%0,%1,%2,%3};"
        : "+f"(d[0]), "+f"(d[1]), "+f"(d[2]), "+f"(d[3])
        : "r"(a0), "r"(a1), "r"(a2), "r"(a3), "r"(b0), "r"(b1));
}
__device__ __forceinline__ void ldmatrix_x4(uint32_t& a0, uint32_t& a1,
                                            uint32_t& a2, uint32_t& a3, uint32_t addr) {
    asm volatile("ldmatrix.sync.aligned.m8n8.x4.shared.b16 {%0,%1,%2,%3}, [%4];"
                 : "=r"(a0), "=r"(a1), "=r"(a2), "=r"(a3) : "r"(addr));
}
__device__ __forceinline__ uint32_t ldmA_base(uint32_t AhAddr, int warp, int lane) {
    int row = warp * 16 + ((lane >> 3) & 1) * 8 + (lane & 7);
    return AhAddr + (uint32_t)row * 144u + (uint32_t)((lane >> 4) & 1) * 16u;
}
// GEMM: ldmatrix A + paired-u64 B: Wp[(n*4 + k16)*32 + lane]
__device__ __forceinline__ void gemm16p(uint32_t aBase,
                                        const u64* __restrict__ Wp,
                                        int lane, float acc[8][4]) {
    #pragma unroll
    for (int k16 = 0; k16 < 4; k16++) {
        uint32_t a0, a1, a2, a3;
        ldmatrix_x4(a0, a1, a2, a3, aBase + (uint32_t)k16 * 32u);
        #pragma unroll
        for (int n = 0; n < 8; n++) {
            u64 w = Wp[(n * 4 + k16) * 32 + lane];
            mma_f16(acc[n], a0, a1, a2, a3, (uint32_t)w, (uint32_t)(w >> 32));
        }
    }
}
// GEMM: register A (D->A direct pass) + paired-u64 B
__device__ __forceinline__ void gemm16r(const uint32_t ar[4][4],
                                        const u64* __restrict__ Wp,
                                        int lane, float acc[8][4]) {
    #pragma unroll
    for (int k16 = 0; k16 < 4; k16++) {
        #pragma unroll
        for (int n = 0; n < 8; n++) {
            u64 w = Wp[(n * 4 + k16) * 32 + lane];
            mma_f16(acc[n], ar[k16][0], ar[k16][1], ar[k16][2], ar[k16][3],
                    (uint32_t)w, (uint32_t)(w >> 32));
        }
    }
}
// build paired-B fragment table from a row-major [k][n] fp32 weight
__device__ __forceinline__ u64 pairB(const float* W, int i) {
    int k16 = (i >> 5) & 3, ln = i & 31;
    int n = ((i >> 7) << 3) + (ln >> 2);
    int h = k16 * 8 + (ln & 3);
    uint32_t b0 = pack_h2(W[(2 * h) * 64 + n],     W[(2 * h + 1) * 64 + n]);
    uint32_t b1 = pack_h2(W[(2 * h + 8) * 64 + n], W[(2 * h + 9) * 64 + n]);
    return ((u64)b1 << 32) | b0;
}

// ================= node kernel: f16 mma, reg-chained GEMMs, f16 outputs =================
struct NSmem {
    u64 Wip[1024], Wsp[1024], Wdp[1024], Wlp[1024];
    uint32_t Ah[128 * 36];
    float bin[64], bl[64];
};

__global__ __launch_bounds__(256, 2) void node_mma_kernel(
    const float* __restrict__ x,
    const float* __restrict__ Win, const float* __restrict__ bin,
    const float* __restrict__ Wsrc, const float* __restrict__ Wdst,
    const float* __restrict__ Wlin, const float* __restrict__ blin, int nn)
{
    extern __shared__ char raw[];
    NSmem& s = *reinterpret_cast<NSmem*>(raw);
    int tid = threadIdx.x;
    for (int i = tid; i < 1024; i += 256) {
        s.Wip[i] = pairB(Win, i);
        s.Wsp[i] = pairB(Wsrc, i);
        s.Wdp[i] = pairB(Wdst, i);
        s.Wlp[i] = pairB(Wlin, i);
    }
    if (tid < 64) { s.bin[tid] = bin[tid]; s.bl[tid] = blin[tid]; }
    __syncthreads();

    int warp = tid >> 5, lane = tid & 31;
    int wr0 = warp * 16 + (lane >> 2);
    int wr1 = wr0 + 8;
    uint32_t aBase = ldmA_base(smem_u32(s.Ah), warp, lane);
    int ntiles = (nn + 127) / 128;

    for (int tile = blockIdx.x; tile < ntiles; tile += gridDim.x) {
        {
            int row = tid >> 1, h = tid & 1;
            int node = tile * 128 + row;
            if (node < nn) {
                const float4* xr = reinterpret_cast<const float4*>(&x[node * 64 + h * 32]);
                #pragma unroll
                for (int j = 0; j < 8; j++) {
                    float4 v = xr[j];
                    s.Ah[row * 36 + h * 16 + j * 2]     = pack_h2(v.x, v.y);
                    s.Ah[row * 36 + h * 16 + j * 2 + 1] = pack_h2(v.z, v.w);
                }
            } else {
                #pragma unroll
                for (int j = 0; j < 16; j++) s.Ah[row * 36 + h * 16 + j] = 0u;
            }
        }
        __syncwarp();

        float acc[8][4];
        #pragma unroll
        for (int n = 0; n < 8; n++) { acc[n][0] = acc[n][1] = acc[n][2] = acc[n][3] = 0.f; }
        gemm16p(aBase, s.Wip, lane, acc);

        // h = relu(acc + bin) -> A registers (D->A direct)
        uint32_t ar[4][4];
        #pragma unroll
        for (int n = 0; n < 8; n++) {
            int colb = n * 8 + (lane & 3) * 2;
            float2 bb = *reinterpret_cast<const float2*>(&s.bin[colb]);
            ar[n >> 1][(n & 1) * 2 + 0] =
                pack_h2(fmaxf(acc[n][0] + bb.x, 0.f), fmaxf(acc[n][1] + bb.y, 0.f));
            ar[n >> 1][(n & 1) * 2 + 1] =
                pack_h2(fmaxf(acc[n][2] + bb.x, 0.f), fmaxf(acc[n][3] + bb.y, 0.f));
        }

        int node0 = tile * 128 + wr0;
        int node1 = tile * 128 + wr1;
        bool n0ok = node0 < nn, n1ok = node1 < nn;

        #pragma unroll
        for (int n = 0; n < 8; n++) { acc[n][0] = acc[n][1] = acc[n][2] = acc[n][3] = 0.f; }
        gemm16r(ar, s.Wsp, lane, acc);
        #pragma unroll
        for (int n = 0; n < 8; n++) {
            int ci = n * 4 + (lane & 3);
            if (n0ok) g_asrc[node0 * 32 + ci] = pack_h2(acc[n][0], acc[n][1]);
            if (n1ok) g_asrc[node1 * 32 + ci] = pack_h2(acc[n][2], acc[n][3]);
        }

        #pragma unroll
        for (int n = 0; n < 8; n++) { acc[n][0] = acc[n][1] = acc[n][2] = acc[n][3] = 0.f; }
        gemm16r(ar, s.Wdp, lane, acc);
        #pragma unroll
        for (int n = 0; n < 8; n++) {
            int ci = n * 4 + (lane & 3);
            if (n0ok) g_adst[node0 * 32 + ci] = pack_h2(acc[n][0], acc[n][1]);
            if (n1ok) g_adst[node1 * 32 + ci] = pack_h2(acc[n][2], acc[n][3]);
        }

        #pragma unroll
        for (int n = 0; n < 8; n++) { acc[n][0] = acc[n][1] = acc[n][2] = acc[n][3] = 0.f; }
        gemm16r(ar, s.Wlp, lane, acc);
        #pragma unroll
        for (int n = 0; n < 8; n++) {
            int colb = n * 8 + (lane & 3) * 2;
            int ci = n * 4 + (lane & 3);
            float2 bb = *reinterpret_cast<const float2*>(&s.bl[colb]);
            if (n0ok) g_v[node0 * 32 + ci] = pack_h2(acc[n][0] + bb.x, acc[n][1] + bb.y);
            if (n1ok) g_v[node1 * 32 + ci] = pack_h2(acc[n][2] + bb.x, acc[n][3] + bb.y);
        }

        {
            float* base = &g_nd[(size_t)tile * 128 * 128];
            for (int i = tid; i < 4096; i += 256) {
                int node = tile * 128 + (i >> 5);
                if (node < nn)
                    *reinterpret_cast<float4*>(base + i * 4) = make_float4(0.f, 0.f, 0.f, 0.f);
            }
        }
        __syncwarp();
    }
}

// ================= edge kernel: reg-chained GEMMs + f16 gathers =================
struct ESmem {
    u64 W2p[1024], W3p[1024], W4p[1024];
    float Wp1[192], b1[64], b2[64], b3[64], b4[64];
    float px[128], py[128], pz[128];
    int si[128], di[128];
};

__global__ __launch_bounds__(256, 2) void edge_mma_kernel(
    const float* __restrict__ pos, const int* __restrict__ ei,
    const float* __restrict__ Wp1, const float* __restrict__ bp1,
    const float* __restrict__ Wp2, const float* __restrict__ bp2,
    const float* __restrict__ Wa1, const float* __restrict__ ba1,
    const float* __restrict__ Wa2, const float* __restrict__ ba2, int ne)
{
    extern __shared__ char raw[];
    ESmem& s = *reinterpret_cast<ESmem*>(raw);
    int tid = threadIdx.x;

    for (int i = tid; i < 1024; i += 256) {
        s.W2p[i] = pairB(Wp2, i);
        s.W3p[i] = pairB(Wa1, i);
        s.W4p[i] = pairB(Wa2, i);
    }
    if (tid < 192) s.Wp1[tid] = Wp1[tid];
    if (tid < 64) { s.b1[tid] = bp1[tid]; s.b2[tid] = bp2[tid]; s.b3[tid] = ba1[tid]; s.b4[tid] = ba2[tid]; }
    __syncthreads();

    int warp = tid >> 5, lane = tid & 31;
    int ntiles = (ne + 127) / 128;

    for (int tile = blockIdx.x; tile < ntiles; tile += gridDim.x) {
        // ---- per-warp meta: lanes 0-15 load this warp's 16 edge-rows ----
        if (lane < 16) {
            int row = warp * 16 + lane;
            int ed = tile * 128 + row;
            int si = 0, di = 0;
            float p0 = 0.f, p1 = 0.f, p2 = 0.f;
            if (ed < ne) {
                si = ei[ed]; di = ei[ne + ed];
                p0 = pos[di * 3 + 0] - pos[si * 3 + 0];
                p1 = pos[di * 3 + 1] - pos[si * 3 + 1];
                p2 = pos[di * 3 + 2] - pos[si * 3 + 2];
            }
            s.si[row] = si; s.di[row] = di;
            s.px[row] = p0; s.py[row] = p1; s.pz[row] = p2;
        }
        __syncwarp();

        int wr0 = warp * 16 + (lane >> 2);
        int wr1 = wr0 + 8;
        int si0 = s.si[wr0], di0 = s.di[wr0];
        int si1 = s.si[wr1], di1 = s.di[wr1];

        // ---- stage0: h1 = relu(pd @ Wp1 + b1) directly in A-fragment registers ----
        uint32_t ar[4][4];
        {
            float pa0 = s.px[wr0], pa1 = s.py[wr0], pa2 = s.pz[wr0];
            float pb0 = s.px[wr1], pb1 = s.py[wr1], pb2 = s.pz[wr1];
            #pragma unroll
            for (int n = 0; n < 8; n++) {
                int c = n * 8 + (lane & 3) * 2;
                float2 w0 = *reinterpret_cast<const float2*>(&s.Wp1[c]);
                float2 w1 = *reinterpret_cast<const float2*>(&s.Wp1[64 + c]);
                float2 w2 = *reinterpret_cast<const float2*>(&s.Wp1[128 + c]);
                float2 bb = *reinterpret_cast<const float2*>(&s.b1[c]);
                float h00 = fmaxf(fmaf(pa2, w2.x, fmaf(pa1, w1.x, fmaf(pa0, w0.x, bb.x))), 0.f);
                float h01 = fmaxf(fmaf(pa2, w2.y, fmaf(pa1, w1.y, fmaf(pa0, w0.y, bb.y))), 0.f);
                float h10 = fmaxf(fmaf(pb2, w2.x, fmaf(pb1, w1.x, fmaf(pb0, w0.x, bb.x))), 0.f);
                float h11 = fmaxf(fmaf(pb2, w2.y, fmaf(pb1, w1.y, fmaf(pb0, w0.y, bb.y))), 0.f);
                ar[n >> 1][(n & 1) * 2 + 0] = pack_h2(h00, h01);
                ar[n >> 1][(n & 1) * 2 + 1] = pack_h2(h10, h11);
            }
        }

        float acc[8][4];
        #pragma unroll
        for (int n = 0; n < 8; n++) { acc[n][0] = acc[n][1] = acc[n][2] = acc[n][3] = 0.f; }
        gemm16r(ar, s.W2p, lane, acc);

        // ---- epi1: delta = relu(.+b2) -> regs; q = adst-asrc+delta -> A regs (f16 gathers) ----
        float dl[8][4];
        #pragma unroll
        for (int n = 0; n < 8; n++) {
            int colb = n * 8 + (lane & 3) * 2;
            int ci = n * 4 + (lane & 3);
            float2 b2v = *reinterpret_cast<const float2*>(&s.b2[colb]);
            float2 ad0 = unpack_h2(g_adst[di0 * 32 + ci]);
            float2 as0 = unpack_h2(g_asrc[si0 * 32 + ci]);
            dl[n][0] = fmaxf(acc[n][0] + b2v.x, 0.f);
            dl[n][1] = fmaxf(acc[n][1] + b2v.y, 0.f);
            ar[n >> 1][(n & 1) * 2 + 0] =
                pack_h2(ad0.x - as0.x + dl[n][0], ad0.y - as0.y + dl[n][1]);
            float2 ad1 = unpack_h2(g_adst[di1 * 32 + ci]);
            float2 as1 = unpack_h2(g_asrc[si1 * 32 + ci]);
            dl[n][2] = fmaxf(acc[n][2] + b2v.x, 0.f);
            dl[n][3] = fmaxf(acc[n][3] + b2v.y, 0.f);
            ar[n >> 1][(n & 1) * 2 + 1] =
                pack_h2(ad1.x - as1.x + dl[n][2], ad1.y - as1.y + dl[n][3]);
        }

        #pragma unroll
        for (int n = 0; n < 8; n++) { acc[n][0] = acc[n][1] = acc[n][2] = acc[n][3] = 0.f; }
        gemm16r(ar, s.W3p, lane, acc);

        // ---- epi2: t = relu(.+b3) -> A regs ----
        #pragma unroll
        for (int n = 0; n < 8; n++) {
            int colb = n * 8 + (lane & 3) * 2;
            float2 b3v = *reinterpret_cast<const float2*>(&s.b3[colb]);
            ar[n >> 1][(n & 1) * 2 + 0] =
                pack_h2(fmaxf(acc[n][0] + b3v.x, 0.f), fmaxf(acc[n][1] + b3v.y, 0.f));
            ar[n >> 1][(n & 1) * 2 + 1] =
                pack_h2(fmaxf(acc[n][2] + b3v.x, 0.f), fmaxf(acc[n][3] + b3v.y, 0.f));
        }

        // ---- prefetch v[src] (f16, covers final GEMM latency) ----
        float2 vv0[8], vv1[8];
        #pragma unroll
        for (int n = 0; n < 8; n++) {
            int ci = n * 4 + (lane & 3);
            vv0[n] = unpack_h2(g_v[si0 * 32 + ci]);
            vv1[n] = unpack_h2(g_v[si1 * 32 + ci]);
        }

        #pragma unroll
        for (int n = 0; n < 8; n++) { acc[n][0] = acc[n][1] = acc[n][2] = acc[n][3] = 0.f; }
        gemm16r(ar, s.W4p, lane, acc);

        // ---- epi3: p = fexp(relu(.+b4)); num = p*(v+delta); vector RED ----
        bool v0 = (tile * 128 + wr0) < ne;
        bool v1 = (tile * 128 + wr1) < ne;
        bool even = ((lane & 1) == 0);
        #pragma unroll
        for (int n = 0; n < 8; n++) {
            int colb = n * 8 + (lane & 3) * 2;
            float2 b4v = *reinterpret_cast<const float2*>(&s.b4[colb]);
            {
                float p0 = fexp(fmaxf(acc[n][0] + b4v.x, 0.f));
                float p1 = fexp(fmaxf(acc[n][1] + b4v.y, 0.f));
                float num0 = p0 * (vv0[n].x + dl[n][0]);
                float num1 = p1 * (vv0[n].y + dl[n][1]);
                float sa = even ? p0 : num0;
                float sb = even ? p1 : num1;
                float ra = __shfl_xor_sync(0xffffffffu, sa, 1);
                float rb = __shfl_xor_sync(0xffffffffu, sb, 1);
                if (v0) {
                    float* nd = &g_nd[di0 * 128];
                    if (even) red_v4(&nd[colb], num0, num1, ra, rb);
                    else      red_v4(&nd[64 + colb - 2], ra, rb, p0, p1);
                }
            }
            {
                float p0 = fexp(fmaxf(acc[n][2] + b4v.x, 0.f));
                float p1 = fexp(fmaxf(acc[n][3] + b4v.y, 0.f));
                float num0 = p0 * (vv1[n].x + dl[n][2]);
                float num1 = p1 * (vv1[n].y + dl[n][3]);
                float sa = even ? p0 : num0;
                float sb = even ? p1 : num1;
                float ra = __shfl_xor_sync(0xffffffffu, sa, 1);
                float rb = __shfl_xor_sync(0xffffffffu, sb, 1);
                if (v1) {
                    float* nd = &g_nd[di1 * 128];
                    if (even) red_v4(&nd[colb], num0, num1, ra, rb);
                    else      red_v4(&nd[64 + colb - 2], ra, rb, p0, p1);
                }
            }
        }
        __syncwarp();
    }
}

// ================= out kernel =================
struct OutSmem {
    float W[4096];
    float b[64];
    float rs[8][64];
};

__global__ __launch_bounds__(256, 3) void out_kernel(
    const float* __restrict__ Wout, const float* __restrict__ bout,
    float* __restrict__ out, int nn)
{
    extern __shared__ char raw[];
    OutSmem& s = *reinterpret_cast<OutSmem*>(raw);
    int tid = threadIdx.x;
    for (int i = tid; i < 4096; i += 256) s.W[i] = Wout[i];
    if (tid < 64) s.b[tid] = bout[tid];
    __syncthreads();

    int warp = tid >> 5, lane = tid & 31, c0 = lane * 2;
    int totW = (gridDim.x * 256) >> 5;
    for (int node = (blockIdx.x * 256 + tid) >> 5; node < nn; node += totW) {
        float2 nm = *reinterpret_cast<float2*>(&g_nd[node * 128 + c0]);
        float2 dn = *reinterpret_cast<float2*>(&g_nd[node * 128 + 64 + c0]);
        float r0 = nm.x / (dn.x + 1e-16f);
        float r1 = nm.y / (dn.y + 1e-16f);
        s.rs[warp][c0] = r0; s.rs[warp][c0 + 1] = r1;
        __syncwarp();
        float o0 = s.b[c0], o1 = s.b[c0 + 1];
        #pragma unroll 16
        for (int k = 0; k < 64; k++) {
            float rk = s.rs[warp][k];
            float2 w = *reinterpret_cast<float2*>(&s.W[k * 64 + c0]);
            o0 = fmaf(rk, w.x, o0); o1 = fmaf(rk, w.y, o1);
        }
        *reinterpret_cast<float2*>(&out[node * 64 + c0]) =
            make_float2(fmaxf(o0, 0.f), fmaxf(o1, 0.f));
        __syncwarp();
    }
}

// ================= launch =================
extern "C" void kernel_launch(void* const* d_in, const int* in_sizes, int n_in,
                              void* d_out, int out_size)
{
    const float* x     = (const float*)d_in[0];
    const float* pos   = (const float*)d_in[1];
    const float* W_in  = (const float*)d_in[2];
    const float* b_in  = (const float*)d_in[3];
    const float* W_src = (const float*)d_in[4];
    const float* W_dst = (const float*)d_in[5];
    const float* W_lin = (const float*)d_in[6];
    const float* b_lin = (const float*)d_in[7];
    const float* Wp1   = (const float*)d_in[8];
    const float* bp1   = (const float*)d_in[9];
    const float* Wp2   = (const float*)d_in[10];
    const float* bp2   = (const float*)d_in[11];
    const float* Wa1   = (const float*)d_in[12];
    const float* ba1   = (const float*)d_in[13];
    const float* Wa2   = (const float*)d_in[14];
    const float* ba2   = (const float*)d_in[15];
    const float* W_out = (const float*)d_in[16];
    const float* b_out = (const float*)d_in[17];
    const int*   ei    = (const int*)d_in[18];
    float* out = (float*)d_out;

    int nn = in_sizes[0] / 64;
    int ne = in_sizes[18] / 2;

    cudaFuncSetAttribute(node_mma_kernel, cudaFuncAttributeMaxDynamicSharedMemorySize, (int)sizeof(NSmem));
    cudaFuncSetAttribute(edge_mma_kernel, cudaFuncAttributeMaxDynamicSharedMemorySize, (int)sizeof(ESmem));
    cudaFuncSetAttribute(out_kernel,  cudaFuncAttributeMaxDynamicSharedMemorySize, (int)sizeof(OutSmem));

    node_mma_kernel<<<296, 256, sizeof(NSmem)>>>(x, W_in, b_in, W_src, W_dst, W_lin, b_lin, nn);
    edge_mma_kernel<<<296, 256, sizeof(ESmem)>>>(pos, ei, Wp1, bp1, Wp2, bp2, Wa1, ba1, Wa2, ba2, ne);
    out_kernel<<<592, 256, sizeof(OutSmem)>>>(W_out, b_out, out, nn);
}